// round 11
// baseline (speedup 1.0000x reference)
#include <cuda_runtime.h>
#include <cuda_fp16.h>
#include <cstdint>

#define D_MODEL 768
#define N_HEADS 12
#define BATCH 2
#define SEQ 4096
#define M_TOT 8192
// 1/sqrt(64) * log2(e) folded into Q at GEMM time (softmax done in base-2)
#define QSCALE 0.1803368801f

// ---------------------------------------------------------------------------
// Scratch lives inside d_out (24 MiB), 8192 regions x 3072 B:
//   [ +0,    +1536) : Q fp16 (written by qkv gemm) then ATT fp16 (overwritten
//                     in-place by attn for its own rows/head slice only)
//   [ +1536, +3072) : striped K/V pool (one batch), chunk c = h*4096+t:
//                     addr = (c/6)*3072 + 1536 + (c%6)*256  (K 128B | V 128B)
// ---------------------------------------------------------------------------

__device__ __forceinline__ unsigned packh2(float a, float b) {
    unsigned lo = (unsigned)__half_as_ushort(__float2half_rn(a));
    unsigned hi = (unsigned)__half_as_ushort(__float2half_rn(b));
    return lo | (hi << 16);
}
__device__ __forceinline__ float ex2(float x) {
    float y; asm("ex2.approx.f32 %0, %1;" : "=f"(y) : "f"(x)); return y;
}
__device__ __forceinline__ void mma16816(float* d, const uint32_t* a,
                                         const uint32_t* b) {
    asm volatile(
        "mma.sync.aligned.m16n8k16.row.col.f32.f16.f16.f32 "
        "{%0,%1,%2,%3}, {%4,%5,%6,%7}, {%8,%9}, {%0,%1,%2,%3};"
        : "+f"(d[0]), "+f"(d[1]), "+f"(d[2]), "+f"(d[3])
        : "r"(a[0]), "r"(a[1]), "r"(a[2]), "r"(a[3]), "r"(b[0]), "r"(b[1]));
}
__device__ __forceinline__ void ldsm_x4(uint32_t& r0, uint32_t& r1,
                                        uint32_t& r2, uint32_t& r3,
                                        uint32_t addr) {
    asm volatile("ldmatrix.sync.aligned.m8n8.x4.shared.b16 {%0,%1,%2,%3}, [%4];"
                 : "=r"(r0), "=r"(r1), "=r"(r2), "=r"(r3) : "r"(addr));
}
__device__ __forceinline__ void ldsm_x4_t(uint32_t& r0, uint32_t& r1,
                                          uint32_t& r2, uint32_t& r3,
                                          uint32_t addr) {
    asm volatile("ldmatrix.sync.aligned.m8n8.x4.trans.shared.b16 {%0,%1,%2,%3}, [%4];"
                 : "=r"(r0), "=r"(r1), "=r"(r2), "=r"(r3) : "r"(addr));
}
__device__ __forceinline__ void cp16(uint32_t smem, const void* g) {
    asm volatile("cp.async.ca.shared.global [%0], [%1], 16;" :: "r"(smem), "l"(g));
}
__device__ __forceinline__ void cp4(uint32_t smem, const void* g) {
    asm volatile("cp.async.ca.shared.global [%0], [%1], 4;" :: "r"(smem), "l"(g));
}

// ---------------------------------------------------------------------------
// Kernel 1 — HMMA QKV GEMM, double-buffered pipeline (unchanged from R10).
// ---------------------------------------------------------------------------
__global__ __launch_bounds__(256)
void qkv_hmma_kernel(const float* __restrict__ x,
                     const float* __restrict__ W_attn,
                     const float* __restrict__ b_attn,
                     char* __restrict__ dbase, int b)
{
    __shared__ __half As[2][128][40];
    __shared__ __half Wt[2][128][40];

    const int tid  = threadIdx.x;
    const int warp = tid >> 5, lane = tid & 31;
    const int wm = warp & 3, wn = warp >> 2;
    const int lr = lane >> 2;
    const int koff = (lane & 3) * 2;
    const int rowBase = blockIdx.y * 128;
    const int colBase = blockIdx.x * 128;
    const float* A = x + (size_t)b * SEQ * D_MODEL;

    float acc[2][8][4];
#pragma unroll
    for (int mt = 0; mt < 2; mt++)
#pragma unroll
        for (int nt = 0; nt < 8; nt++)
#pragma unroll
            for (int j = 0; j < 4; j++) acc[mt][nt][j] = 0.f;

    float4 a_pre[4], w_pre[4];

#define QKV_LDG(IT) do {                                                        \
    int k0_ = (IT) * 32;                                                        \
    _Pragma("unroll")                                                           \
    for (int i = 0; i < 4; i++) {                                               \
        int idx = tid + i * 256;                                                \
        int r = idx >> 3, c4 = (idx & 7) << 2;                                  \
        a_pre[i] = *(const float4*)&A[(size_t)(rowBase + r) * D_MODEL + k0_ + c4]; \
    }                                                                           \
    _Pragma("unroll")                                                           \
    for (int i = 0; i < 4; i++) {                                               \
        int idx = tid + i * 256;                                                \
        int kr = idx >> 5, n4 = (idx & 31) << 2;                                \
        w_pre[i] = *(const float4*)&W_attn[(size_t)(k0_ + kr) * 2304 + colBase + n4]; \
    }                                                                           \
} while (0)

#define QKV_STS(BUF) do {                                                       \
    _Pragma("unroll")                                                           \
    for (int i = 0; i < 4; i++) {                                               \
        int idx = tid + i * 256;                                                \
        int r = idx >> 3, c4 = (idx & 7) << 2;                                  \
        *(uint32_t*)&As[BUF][r][c4]     = packh2(a_pre[i].x, a_pre[i].y);       \
        *(uint32_t*)&As[BUF][r][c4 + 2] = packh2(a_pre[i].z, a_pre[i].w);       \
        int kr = idx >> 5, n4 = (idx & 31) << 2;                                \
        Wt[BUF][n4 + 0][kr] = __float2half_rn(w_pre[i].x);                      \
        Wt[BUF][n4 + 1][kr] = __float2half_rn(w_pre[i].y);                      \
        Wt[BUF][n4 + 2][kr] = __float2half_rn(w_pre[i].z);                      \
        Wt[BUF][n4 + 3][kr] = __float2half_rn(w_pre[i].w);                      \
    }                                                                           \
} while (0)

    QKV_LDG(0);
    QKV_STS(0);
    __syncthreads();

    for (int it = 0; it < 24; ++it) {
        const int cur = it & 1;
        const bool more = (it + 1 < 24);
        if (more) QKV_LDG(it + 1);

#pragma unroll
        for (int kc = 0; kc < 32; kc += 16) {
            uint32_t qa[2][4];
#pragma unroll
            for (int mt = 0; mt < 2; mt++) {
                int r = wm * 32 + mt * 16 + lr;
                qa[mt][0] = *(const uint32_t*)&As[cur][r][kc + koff];
                qa[mt][1] = *(const uint32_t*)&As[cur][r + 8][kc + koff];
                qa[mt][2] = *(const uint32_t*)&As[cur][r][kc + koff + 8];
                qa[mt][3] = *(const uint32_t*)&As[cur][r + 8][kc + koff + 8];
            }
#pragma unroll
            for (int nt = 0; nt < 8; nt++) {
                int n = wn * 64 + nt * 8 + lr;
                uint32_t wb[2];
                wb[0] = *(const uint32_t*)&Wt[cur][n][kc + koff];
                wb[1] = *(const uint32_t*)&Wt[cur][n][kc + koff + 8];
                mma16816(acc[0][nt], qa[0], wb);
                mma16816(acc[1][nt], qa[1], wb);
            }
        }

        if (more) {
            __syncthreads();
            QKV_STS(1 - cur);
            __syncthreads();
        }
    }
#undef QKV_LDG
#undef QKV_STS

#pragma unroll
    for (int nt = 0; nt < 8; nt++) {
        int gcol = colBase + wn * 64 + nt * 8 + (lane & 3) * 2;
        int which = gcol / 768;
        int cc = gcol - which * 768;
        int h = cc >> 6, d0 = cc & 63;
        float b0 = b_attn[gcol], b1 = b_attn[gcol + 1];
        float sc = (which == 0) ? QSCALE : 1.f;
#pragma unroll
        for (int mt = 0; mt < 2; mt++) {
#pragma unroll
            for (int rh = 0; rh < 2; rh++) {
                int t = rowBase + wm * 32 + mt * 16 + lr + rh * 8;
                float v0 = (acc[mt][nt][rh * 2 + 0] + b0) * sc;
                float v1 = (acc[mt][nt][rh * 2 + 1] + b1) * sc;
                char* pa;
                if (which == 0) {
                    pa = dbase + (size_t)(b * SEQ + t) * 3072 + (size_t)(h * 64 + d0) * 2;
                } else {
                    int c = h * SEQ + t;
                    int p = c / 6, s = c - p * 6;
                    pa = dbase + (size_t)p * 3072 + 1536 + s * 256
                       + (which == 2 ? 128 : 0) + d0 * 2;
                }
                *(uint32_t*)pa = packh2(v0, v1);
            }
        }
    }
}

// ---------------------------------------------------------------------------
// Kernel 2 — tensor-core flash attention v2.
// 256 threads (8 warps), Q tile 128 rows, 64-key tiles.
// cp.async double-buffered K/V staging; ldmatrix.x4 for K B-frags,
// ldmatrix.x4.trans for V B-frags (V stored raw [key][dim]).
// Dynamic smem: Qs 128x72 | Ks 2x64x72 | Vs 2x64x72 | msk 2x64 = 55808 B.
// ---------------------------------------------------------------------------
#define ATT_SMEM_BYTES (128 * 72 * 2 + 2 * 64 * 72 * 2 * 2 + 2 * 64 * 4)

__global__ __launch_bounds__(256)
void attn_mma_kernel(const int* __restrict__ attn_mask,
                     char* __restrict__ dbase, int b)
{
    extern __shared__ char smem_raw[];
    __half (*Qs)[72] = (__half(*)[72])smem_raw;
    char* ks_base = smem_raw + 128 * 72 * 2;            // + buf*9216
    char* vs_base = ks_base + 2 * 64 * 72 * 2;          // + buf*9216
    int*  msk     = (int*)(vs_base + 2 * 64 * 72 * 2);  // [buf*64 + cc]

    const int qt   = (int)gridDim.x - 1 - (int)blockIdx.x;  // heavy first
    const int h    = blockIdx.y;
    const int tid  = threadIdx.x;
    const int warp = tid >> 5, lane = tid & 31;
    const int lr   = lane >> 2;
    const int koff = (lane & 3) * 2;

    // ---- stage Q tile (128 rows) ----
#pragma unroll
    for (int i = 0; i < 4; i++) {
        int idx = tid + i * 256;          // 1024 chunks of 16B
        int rr = idx >> 3, c8 = (idx & 7) * 8;
        const char* src = dbase + (size_t)(b * SEQ + qt * 128 + rr) * 3072
                        + (size_t)(h * 64 + c8) * 2;
        *(uint4*)&Qs[rr][c8] = *(const uint4*)src;
    }
    __syncthreads();

    uint32_t qa[4][4];
    const int qr = warp * 16 + lr;
#pragma unroll
    for (int ks = 0; ks < 4; ks++) {
        qa[ks][0] = *(const uint32_t*)&Qs[qr][ks * 16 + koff];
        qa[ks][1] = *(const uint32_t*)&Qs[qr + 8][ks * 16 + koff];
        qa[ks][2] = *(const uint32_t*)&Qs[qr][ks * 16 + koff + 8];
        qa[ks][3] = *(const uint32_t*)&Qs[qr + 8][ks * 16 + koff + 8];
    }

    const int q0 = qt * 128 + qr;
    const int q1 = q0 + 8;
    const int ktmax = 2 * qt + 1;

    float m0 = -1e30f, m1 = -1e30f, l0 = 0.f, l1 = 0.f;
    float O[8][4];
#pragma unroll
    for (int nb = 0; nb < 8; nb++)
#pragma unroll
        for (int j = 0; j < 4; j++) O[nb][j] = 0.f;

    // ---- staging macro: tile KT into buffer BUF via cp.async ----
#define ATT_STAGE(KT, BUF) do {                                                 \
    _Pragma("unroll")                                                           \
    for (int i = 0; i < 2; i++) {                                               \
        int idx = tid + i * 256;            /* 512 chunks of 16B each for K,V */\
        int rr = idx >> 3, c8 = (idx & 7) * 8;                                  \
        int c = h * SEQ + (KT) * 64 + rr;                                       \
        int p = c / 6, s = c - p * 6;                                           \
        const char* base = dbase + (size_t)p * 3072 + 1536 + s * 256;           \
        uint32_t kd = (uint32_t)__cvta_generic_to_shared(                       \
            ks_base + (BUF) * 9216 + (rr * 72 + c8) * 2);                       \
        uint32_t vd = (uint32_t)__cvta_generic_to_shared(                       \
            vs_base + (BUF) * 9216 + (rr * 72 + c8) * 2);                       \
        cp16(kd, base + c8 * 2);                                                \
        cp16(vd, base + 128 + c8 * 2);                                          \
    }                                                                           \
    if (tid < 64) {                                                             \
        uint32_t md = (uint32_t)__cvta_generic_to_shared(&msk[(BUF) * 64 + tid]); \
        cp4(md, &attn_mask[b * SEQ + (KT) * 64 + tid]);                         \
    }                                                                           \
    asm volatile("cp.async.commit_group;");                                     \
} while (0)

    ATT_STAGE(0, 0);

    for (int kt = 0; kt <= ktmax; kt++) {
        const int cur = kt & 1;
        __syncthreads();                 // prev compute done before overwrite
        if (kt < ktmax) {
            ATT_STAGE(kt + 1, 1 - cur);
            asm volatile("cp.async.wait_group 1;");
        } else {
            asm volatile("cp.async.wait_group 0;");
        }
        __syncthreads();

        const __half (*Ks)[72] = (const __half(*)[72])(ks_base + cur * 9216);
        const __half (*Vs)[72] = (const __half(*)[72])(vs_base + cur * 9216);
        const int* mk = &msk[cur * 64];

        // ---- S = Q K^T (K B-frags via ldmatrix.x4) ----
        float S[8][4];
#pragma unroll
        for (int nb = 0; nb < 8; nb++)
#pragma unroll
            for (int j = 0; j < 4; j++) S[nb][j] = 0.f;

        const int lm = lane >> 3, lrr = lane & 7;   // ldmatrix addressing
#pragma unroll
        for (int ks = 0; ks < 4; ks++) {
#pragma unroll
            for (int nbp = 0; nbp < 4; nbp++) {
                // matrices: m0/m1 = nb=2*nbp (k lo/hi), m2/m3 = nb+1
                int n = nbp * 16 + (lm >> 1) * 8 + lrr;
                int k = ks * 16 + (lm & 1) * 8;
                uint32_t addr = (uint32_t)__cvta_generic_to_shared(&Ks[n][k]);
                uint32_t r0, r1, r2, r3;
                ldsm_x4(r0, r1, r2, r3, addr);
                uint32_t kb0[2] = {r0, r1}, kb1[2] = {r2, r3};
                mma16816(S[2 * nbp],     qa[ks], kb0);
                mma16816(S[2 * nbp + 1], qa[ks], kb1);
            }
        }

        // ---- mask + online softmax (base-2, scale prefolded) ----
        const bool diag = (kt >= 2 * qt);
        float mx0 = -1e30f, mx1 = -1e30f;
#pragma unroll
        for (int nb = 0; nb < 8; nb++) {
            int cc = nb * 8 + koff;
            int kj = kt * 64 + cc;
            bool ok0 = mk[cc] != 0, ok1 = mk[cc + 1] != 0;
            bool a00 = ok0 && (!diag || kj     <= q0);
            bool a01 = ok1 && (!diag || kj + 1 <= q0);
            bool a10 = ok0 && (!diag || kj     <= q1);
            bool a11 = ok1 && (!diag || kj + 1 <= q1);
            S[nb][0] = a00 ? S[nb][0] : -1e30f;
            S[nb][1] = a01 ? S[nb][1] : -1e30f;
            S[nb][2] = a10 ? S[nb][2] : -1e30f;
            S[nb][3] = a11 ? S[nb][3] : -1e30f;
            mx0 = fmaxf(mx0, fmaxf(S[nb][0], S[nb][1]));
            mx1 = fmaxf(mx1, fmaxf(S[nb][2], S[nb][3]));
        }
        mx0 = fmaxf(mx0, __shfl_xor_sync(0xffffffffu, mx0, 1));
        mx0 = fmaxf(mx0, __shfl_xor_sync(0xffffffffu, mx0, 2));
        mx1 = fmaxf(mx1, __shfl_xor_sync(0xffffffffu, mx1, 1));
        mx1 = fmaxf(mx1, __shfl_xor_sync(0xffffffffu, mx1, 2));
        float m0n = fmaxf(m0, mx0), m1n = fmaxf(m1, mx1);
        float corr0 = ex2(m0 - m0n), corr1 = ex2(m1 - m1n);
        m0 = m0n; m1 = m1n;

        uint32_t pa[4][4];
        float sum0 = 0.f, sum1 = 0.f;
#pragma unroll
        for (int nb = 0; nb < 8; nb++) {
            float p00 = ex2(S[nb][0] - m0), p01 = ex2(S[nb][1] - m0);
            float p10 = ex2(S[nb][2] - m1), p11 = ex2(S[nb][3] - m1);
            sum0 += p00 + p01; sum1 += p10 + p11;
            int ksv = nb >> 1, hi = (nb & 1) * 2;
            pa[ksv][hi + 0] = packh2(p00, p01);
            pa[ksv][hi + 1] = packh2(p10, p11);
        }
        l0 = l0 * corr0 + sum0;
        l1 = l1 * corr1 + sum1;
#pragma unroll
        for (int nb = 0; nb < 8; nb++) {
            O[nb][0] *= corr0; O[nb][1] *= corr0;
            O[nb][2] *= corr1; O[nb][3] *= corr1;
        }

        // ---- O += P V (V B-frags via ldmatrix.x4.trans on raw V) ----
#pragma unroll
        for (int ksv = 0; ksv < 4; ksv++) {
#pragma unroll
            for (int nbp = 0; nbp < 4; nbp++) {
                // m0/m1 = nb=2*nbp (key lo/hi), m2/m3 = nb+1
                int key = ksv * 16 + (lm & 1) * 8 + lrr;
                int dim = nbp * 16 + (lm >> 1) * 8;
                uint32_t addr = (uint32_t)__cvta_generic_to_shared(&Vs[key][dim]);
                uint32_t r0, r1, r2, r3;
                ldsm_x4_t(r0, r1, r2, r3, addr);
                uint32_t vb0[2] = {r0, r1}, vb1[2] = {r2, r3};
                mma16816(O[2 * nbp],     pa[ksv], vb0);
                mma16816(O[2 * nbp + 1], pa[ksv], vb1);
            }
        }
    }
#undef ATT_STAGE

    // ---- epilogue ----
    l0 += __shfl_xor_sync(0xffffffffu, l0, 1);
    l0 += __shfl_xor_sync(0xffffffffu, l0, 2);
    l1 += __shfl_xor_sync(0xffffffffu, l1, 1);
    l1 += __shfl_xor_sync(0xffffffffu, l1, 2);
    float inv0 = 1.f / l0, inv1 = 1.f / l1;

    char* r0p = dbase + (size_t)(b * SEQ + q0) * 3072 + (size_t)(h * 64 + koff) * 2;
    char* r1p = dbase + (size_t)(b * SEQ + q1) * 3072 + (size_t)(h * 64 + koff) * 2;
#pragma unroll
    for (int nb = 0; nb < 8; nb++) {
        *(uint32_t*)(r0p + nb * 16) = packh2(O[nb][0] * inv0, O[nb][1] * inv0);
        *(uint32_t*)(r1p + nb * 16) = packh2(O[nb][2] * inv1, O[nb][3] * inv1);
    }
}

// ---------------------------------------------------------------------------
// Kernel 3 — HMMA proj GEMM with stripe ownership (unchanged from R10).
// ---------------------------------------------------------------------------
#define PROJ_SMEM_BYTES (64 * 776 * 2 + 2 * 128 * 40 * 2)

__global__ __launch_bounds__(256)
void proj_hmma_kernel(const char* __restrict__ att_base,
                      const float* __restrict__ W_proj,
                      const float* __restrict__ b_proj,
                      float* __restrict__ out)
{
    extern __shared__ char smem_raw[];
    __half (*ATTs)[776] = (__half(*)[776])smem_raw;
    __half (*Wt)[40]    = (__half(*)[40])(smem_raw + 64 * 776 * 2);

    const int tid  = threadIdx.x;
    const int warp = tid >> 5, lane = tid & 31;
    const int wm = warp & 3, wn = warp >> 2;
    const int lr = lane >> 2;
    const int koff = (lane & 3) * 2;
    const int rowBase = blockIdx.x * 64;

#pragma unroll
    for (int i = 0; i < 24; i++) {
        int idx = tid + i * 256;
        int r = idx / 96, c8 = (idx - r * 96) * 8;
        *(uint4*)&ATTs[r][c8] =
            *(const uint4*)(att_base + (size_t)(rowBase + r) * 3072 + (size_t)c8 * 2);
    }

    float4 w_pre[4];

#define PROJ_LDG(IT, COLB) do {                                                 \
    int k0_ = (IT) * 32;                                                        \
    _Pragma("unroll")                                                           \
    for (int i = 0; i < 4; i++) {                                               \
        int idx = tid + i * 256;                                                \
        int kr = idx >> 5, n4 = (idx & 31) << 2;                                \
        w_pre[i] = *(const float4*)&W_proj[(size_t)(k0_ + kr) * 768 + (COLB) + n4]; \
    }                                                                           \
} while (0)

#define PROJ_STS(BUF) do {                                                      \
    _Pragma("unroll")                                                           \
    for (int i = 0; i < 4; i++) {                                               \
        int idx = tid + i * 256;                                                \
        int kr = idx >> 5, n4 = (idx & 31) << 2;                                \
        Wt[(BUF) * 128 + n4 + 0][kr] = __float2half_rn(w_pre[i].x);             \
        Wt[(BUF) * 128 + n4 + 1][kr] = __float2half_rn(w_pre[i].y);             \
        Wt[(BUF) * 128 + n4 + 2][kr] = __float2half_rn(w_pre[i].z);             \
        Wt[(BUF) * 128 + n4 + 3][kr] = __float2half_rn(w_pre[i].w);             \
    }                                                                           \
} while (0)

    for (int chunk = 0; chunk < 6; ++chunk) {
        const int colBase = chunk * 128;
        float acc[8][4];
#pragma unroll
        for (int nt = 0; nt < 8; nt++)
#pragma unroll
            for (int j = 0; j < 4; j++) acc[nt][j] = 0.f;

        __syncthreads();
        PROJ_LDG(0, colBase);
        PROJ_STS(0);
        __syncthreads();

        for (int it = 0; it < 24; ++it) {
            const int cur = it & 1;
            const bool more = (it + 1 < 24);
            if (more) PROJ_LDG(it + 1, colBase);

#pragma unroll
            for (int kc = 0; kc < 32; kc += 16) {
                int ak = it * 32 + kc;
                uint32_t aa[4];
                int r = wm * 16 + lr;
                aa[0] = *(const uint32_t*)&ATTs[r][ak + koff];
                aa[1] = *(const uint32_t*)&ATTs[r + 8][ak + koff];
                aa[2] = *(const uint32_t*)&ATTs[r][ak + koff + 8];
                aa[3] = *(const uint32_t*)&ATTs[r + 8][ak + koff + 8];
#pragma unroll
                for (int nt = 0; nt < 8; nt++) {
                    int n = wn * 64 + nt * 8 + lr;
                    uint32_t wb[2];
                    wb[0] = *(const uint32_t*)&Wt[cur * 128 + n][kc + koff];
                    wb[1] = *(const uint32_t*)&Wt[cur * 128 + n][kc + koff + 8];
                    mma16816(acc[nt], aa, wb);
                }
            }

            if (more) {
                __syncthreads();
                PROJ_STS(1 - cur);
                __syncthreads();
            }
        }

#pragma unroll
        for (int nt = 0; nt < 8; nt++) {
            int gcol = colBase + wn * 64 + nt * 8 + koff;
            float b0 = b_proj[gcol], b1 = b_proj[gcol + 1];
#pragma unroll
            for (int rh = 0; rh < 2; rh++) {
                int row = rowBase + wm * 16 + lr + rh * 8;
                float2 o;
                o.x = acc[nt][rh * 2 + 0] + b0;
                o.y = acc[nt][rh * 2 + 1] + b1;
                *(float2*)&out[(size_t)row * 768 + gcol] = o;
            }
        }
    }
#undef PROJ_LDG
#undef PROJ_STS
}

// ---------------------------------------------------------------------------
extern "C" void kernel_launch(void* const* d_in, const int* in_sizes, int n_in,
                              void* d_out, int out_size)
{
    const float* x      = (const float*)d_in[0];
    const int*   amask  = (const int*)d_in[1];
    const float* W_attn = (const float*)d_in[2];
    const float* b_attn = (const float*)d_in[3];
    const float* W_proj = (const float*)d_in[4];
    const float* b_proj = (const float*)d_in[5];
    float*       out    = (float*)d_out;
    char*        dbase  = (char*)d_out;

    cudaFuncSetAttribute(proj_hmma_kernel,
                         cudaFuncAttributeMaxDynamicSharedMemorySize,
                         PROJ_SMEM_BYTES);
    cudaFuncSetAttribute(attn_mma_kernel,
                         cudaFuncAttributeMaxDynamicSharedMemorySize,
                         ATT_SMEM_BYTES);

    for (int b = 0; b < BATCH; b++) {
        qkv_hmma_kernel<<<dim3(2304 / 128, SEQ / 128), 256>>>(x, W_attn, b_attn, dbase, b);
        attn_mma_kernel<<<dim3(SEQ / 128, N_HEADS), 256, ATT_SMEM_BYTES>>>(amask, dbase, b);
    }
    proj_hmma_kernel<<<M_TOT / 64, 256, PROJ_SMEM_BYTES>>>(dbase, W_proj, b_proj, out);
}

// round 12
// speedup vs baseline: 1.0585x; 1.0585x over previous
#include <cuda_runtime.h>
#include <cuda_fp16.h>
#include <cstdint>

#define D_MODEL 768
#define N_HEADS 12
#define BATCH 2
#define SEQ 4096
#define M_TOT 8192
// 1/sqrt(64) * log2(e) folded into Q at GEMM time (softmax done in base-2)
#define QSCALE 0.1803368801f

// ---------------------------------------------------------------------------
// Scratch lives inside d_out (24 MiB), 8192 regions x 3072 B:
//   [ +0,    +1536) : Q fp16 (written by qkv gemm) then ATT fp16 (overwritten
//                     in-place by attn for its own rows/head slice only)
//   [ +1536, +3072) : striped K/V pool (one batch), chunk c = h*4096+t:
//                     addr = (c/6)*3072 + 1536 + (c%6)*256  (K 128B | V 128B)
// ---------------------------------------------------------------------------

__device__ __forceinline__ unsigned packh2(float a, float b) {
    unsigned lo = (unsigned)__half_as_ushort(__float2half_rn(a));
    unsigned hi = (unsigned)__half_as_ushort(__float2half_rn(b));
    return lo | (hi << 16);
}
__device__ __forceinline__ float ex2(float x) {
    float y; asm("ex2.approx.f32 %0, %1;" : "=f"(y) : "f"(x)); return y;
}
__device__ __forceinline__ void mma16816(float* d, const uint32_t* a,
                                         const uint32_t* b) {
    asm volatile(
        "mma.sync.aligned.m16n8k16.row.col.f32.f16.f16.f32 "
        "{%0,%1,%2,%3}, {%4,%5,%6,%7}, {%8,%9}, {%0,%1,%2,%3};"
        : "+f"(d[0]), "+f"(d[1]), "+f"(d[2]), "+f"(d[3])
        : "r"(a[0]), "r"(a[1]), "r"(a[2]), "r"(a[3]), "r"(b[0]), "r"(b[1]));
}
__device__ __forceinline__ void ldsm_x4(uint32_t& r0, uint32_t& r1,
                                        uint32_t& r2, uint32_t& r3,
                                        const void* p) {
    uint32_t addr = (uint32_t)__cvta_generic_to_shared(p);
    asm volatile("ldmatrix.sync.aligned.m8n8.x4.shared.b16 {%0,%1,%2,%3}, [%4];"
                 : "=r"(r0), "=r"(r1), "=r"(r2), "=r"(r3) : "r"(addr));
}
__device__ __forceinline__ void ldsm_x4_t(uint32_t& r0, uint32_t& r1,
                                          uint32_t& r2, uint32_t& r3,
                                          const void* p) {
    uint32_t addr = (uint32_t)__cvta_generic_to_shared(p);
    asm volatile("ldmatrix.sync.aligned.m8n8.x4.trans.shared.b16 {%0,%1,%2,%3}, [%4];"
                 : "=r"(r0), "=r"(r1), "=r"(r2), "=r"(r3) : "r"(addr));
}

// ---------------------------------------------------------------------------
// Kernel 1 — HMMA QKV GEMM, double-buffered, ldmatrix fragment loads.
// BM=128, BN=128, BK=32, 256 thr = 8 warps (4m x 2n), warp tile 32x64.
// ---------------------------------------------------------------------------
__global__ __launch_bounds__(256)
void qkv_hmma_kernel(const float* __restrict__ x,
                     const float* __restrict__ W_attn,
                     const float* __restrict__ b_attn,
                     char* __restrict__ dbase, int b)
{
    __shared__ __half As[2][128][40];
    __shared__ __half Wt[2][128][40];

    const int tid  = threadIdx.x;
    const int warp = tid >> 5, lane = tid & 31;
    const int wm = warp & 3, wn = warp >> 2;
    const int lr = lane >> 2;
    const int lm = lane >> 3, lrr = lane & 7;      // ldmatrix addressing
    const int rowBase = blockIdx.y * 128;
    const int colBase = blockIdx.x * 128;
    const float* A = x + (size_t)b * SEQ * D_MODEL;

    float acc[2][8][4];
#pragma unroll
    for (int mt = 0; mt < 2; mt++)
#pragma unroll
        for (int nt = 0; nt < 8; nt++)
#pragma unroll
            for (int j = 0; j < 4; j++) acc[mt][nt][j] = 0.f;

    float4 a_pre[4], w_pre[4];

#define QKV_LDG(IT) do {                                                        \
    int k0_ = (IT) * 32;                                                        \
    _Pragma("unroll")                                                           \
    for (int i = 0; i < 4; i++) {                                               \
        int idx = tid + i * 256;                                                \
        int r = idx >> 3, c4 = (idx & 7) << 2;                                  \
        a_pre[i] = *(const float4*)&A[(size_t)(rowBase + r) * D_MODEL + k0_ + c4]; \
    }                                                                           \
    _Pragma("unroll")                                                           \
    for (int i = 0; i < 4; i++) {                                               \
        int idx = tid + i * 256;                                                \
        int kr = idx >> 5, n4 = (idx & 31) << 2;                                \
        w_pre[i] = *(const float4*)&W_attn[(size_t)(k0_ + kr) * 2304 + colBase + n4]; \
    }                                                                           \
} while (0)

#define QKV_STS(BUF) do {                                                       \
    _Pragma("unroll")                                                           \
    for (int i = 0; i < 4; i++) {                                               \
        int idx = tid + i * 256;                                                \
        int r = idx >> 3, c4 = (idx & 7) << 2;                                  \
        *(uint32_t*)&As[BUF][r][c4]     = packh2(a_pre[i].x, a_pre[i].y);       \
        *(uint32_t*)&As[BUF][r][c4 + 2] = packh2(a_pre[i].z, a_pre[i].w);       \
        int kr = idx >> 5, n4 = (idx & 31) << 2;                                \
        Wt[BUF][n4 + 0][kr] = __float2half_rn(w_pre[i].x);                      \
        Wt[BUF][n4 + 1][kr] = __float2half_rn(w_pre[i].y);                      \
        Wt[BUF][n4 + 2][kr] = __float2half_rn(w_pre[i].z);                      \
        Wt[BUF][n4 + 3][kr] = __float2half_rn(w_pre[i].w);                      \
    }                                                                           \
} while (0)

    QKV_LDG(0);
    QKV_STS(0);
    __syncthreads();

    for (int it = 0; it < 24; ++it) {
        const int cur = it & 1;
        const bool more = (it + 1 < 24);
        if (more) QKV_LDG(it + 1);

#pragma unroll
        for (int kc = 0; kc < 32; kc += 16) {
            // A-frags: one ldmatrix.x4 per 16-row group.
            // m0=(r0-7,klo) m1=(r8-15,klo) m2=(r0-7,khi) m3=(r8-15,khi)
            uint32_t qa[2][4];
#pragma unroll
            for (int mt = 0; mt < 2; mt++) {
                int r = wm * 32 + mt * 16 + lrr + ((lane >> 3) & 1) * 8;
                int c = kc + (lane >> 4) * 8;
                ldsm_x4(qa[mt][0], qa[mt][1], qa[mt][2], qa[mt][3],
                        &As[cur][r][c]);
            }
            // W B-frags: one ldmatrix.x4 per 16 n-rows (2 nt groups).
#pragma unroll
            for (int nbp = 0; nbp < 4; nbp++) {
                int n = wn * 64 + nbp * 16 + (lm >> 1) * 8 + lrr;
                int k = kc + (lm & 1) * 8;
                uint32_t r0, r1, r2, r3;
                ldsm_x4(r0, r1, r2, r3, &Wt[cur][n][k]);
                uint32_t wb0[2] = {r0, r1}, wb1[2] = {r2, r3};
                mma16816(acc[0][2 * nbp],     qa[0], wb0);
                mma16816(acc[0][2 * nbp + 1], qa[0], wb1);
                mma16816(acc[1][2 * nbp],     qa[1], wb0);
                mma16816(acc[1][2 * nbp + 1], qa[1], wb1);
            }
        }

        if (more) {
            __syncthreads();
            QKV_STS(1 - cur);
            __syncthreads();
        }
    }
#undef QKV_LDG
#undef QKV_STS

#pragma unroll
    for (int nt = 0; nt < 8; nt++) {
        int gcol = colBase + wn * 64 + nt * 8 + (lane & 3) * 2;
        int which = gcol / 768;
        int cc = gcol - which * 768;
        int h = cc >> 6, d0 = cc & 63;
        float b0 = b_attn[gcol], b1 = b_attn[gcol + 1];
        float sc = (which == 0) ? QSCALE : 1.f;
#pragma unroll
        for (int mt = 0; mt < 2; mt++) {
#pragma unroll
            for (int rh = 0; rh < 2; rh++) {
                int t = rowBase + wm * 32 + mt * 16 + lr + rh * 8;
                float v0 = (acc[mt][nt][rh * 2 + 0] + b0) * sc;
                float v1 = (acc[mt][nt][rh * 2 + 1] + b1) * sc;
                char* pa;
                if (which == 0) {
                    pa = dbase + (size_t)(b * SEQ + t) * 3072 + (size_t)(h * 64 + d0) * 2;
                } else {
                    int c = h * SEQ + t;
                    int p = c / 6, s = c - p * 6;
                    pa = dbase + (size_t)p * 3072 + 1536 + s * 256
                       + (which == 2 ? 128 : 0) + d0 * 2;
                }
                *(uint32_t*)pa = packh2(v0, v1);
            }
        }
    }
}

// ---------------------------------------------------------------------------
// Kernel 2 — tensor-core flash attention (R10 shape + ldmatrix loads).
// 128 threads (4 warps), 64-row Q tile, static smem (~28 KB, R10 occupancy).
// K B-frags via ldmatrix.x4; V stored RAW, B-frags via ldmatrix.x4.trans.
// ---------------------------------------------------------------------------
__global__ __launch_bounds__(128)
void attn_mma_kernel(const int* __restrict__ attn_mask,
                     char* __restrict__ dbase, int b)
{
    const int qt   = (int)gridDim.x - 1 - (int)blockIdx.x;  // heavy first
    const int h    = blockIdx.y;
    const int tid  = threadIdx.x;
    const int warp = tid >> 5, lane = tid & 31;
    const int lr   = lane >> 2;
    const int koff = (lane & 3) * 2;
    const int lm = lane >> 3, lrr = lane & 7;

    __shared__ __half Qs[64][72];
    __shared__ __half Ks[64][72];
    __shared__ __half Vs[64][72];        // raw [key][dim]
    __shared__ int    msk[64];

#pragma unroll
    for (int i = 0; i < 4; i++) {
        int idx = tid + i * 128;
        int rr = idx >> 3, c8 = (idx & 7) * 8;
        const char* src = dbase + (size_t)(b * SEQ + qt * 64 + rr) * 3072
                        + (size_t)(h * 64 + c8) * 2;
        *(uint4*)&Qs[rr][c8] = *(const uint4*)src;
    }
    __syncthreads();

    uint32_t qa[4][4];
    const int qr = warp * 16 + lr;
    {
        int r = warp * 16 + lrr + ((lane >> 3) & 1) * 8;
#pragma unroll
        for (int ks = 0; ks < 4; ks++) {
            int c = ks * 16 + (lane >> 4) * 8;
            ldsm_x4(qa[ks][0], qa[ks][1], qa[ks][2], qa[ks][3], &Qs[r][c]);
        }
    }

    const int q0 = qt * 64 + qr;
    const int q1 = q0 + 8;

    float m0 = -1e30f, m1 = -1e30f, l0 = 0.f, l1 = 0.f;
    float O[8][4];
#pragma unroll
    for (int nb = 0; nb < 8; nb++)
#pragma unroll
        for (int j = 0; j < 4; j++) O[nb][j] = 0.f;

    for (int kt = 0; kt <= qt; kt++) {
        __syncthreads();
        // Stage K and V raw (uint4 copies; no scalar transpose).
#pragma unroll
        for (int i = 0; i < 4; i++) {
            int idx = tid + i * 128;
            int rr = idx >> 3, c8 = (idx & 7) * 8;
            int c = h * SEQ + kt * 64 + rr;
            int p = c / 6, s = c - p * 6;
            const char* base = dbase + (size_t)p * 3072 + 1536 + s * 256;
            *(uint4*)&Ks[rr][c8] = *(const uint4*)(base + c8 * 2);
            *(uint4*)&Vs[rr][c8] = *(const uint4*)(base + 128 + c8 * 2);
        }
        if (tid < 64) msk[tid] = attn_mask[b * SEQ + kt * 64 + tid];
        __syncthreads();

        // ---- S = Q K^T (K B-frags via ldmatrix.x4) ----
        float S[8][4];
#pragma unroll
        for (int nb = 0; nb < 8; nb++)
#pragma unroll
            for (int j = 0; j < 4; j++) S[nb][j] = 0.f;

#pragma unroll
        for (int ks = 0; ks < 4; ks++) {
#pragma unroll
            for (int nbp = 0; nbp < 4; nbp++) {
                int n = nbp * 16 + (lm >> 1) * 8 + lrr;
                int k = ks * 16 + (lm & 1) * 8;
                uint32_t r0, r1, r2, r3;
                ldsm_x4(r0, r1, r2, r3, &Ks[n][k]);
                uint32_t kb0[2] = {r0, r1}, kb1[2] = {r2, r3};
                mma16816(S[2 * nbp],     qa[ks], kb0);
                mma16816(S[2 * nbp + 1], qa[ks], kb1);
            }
        }

        // ---- mask + online softmax (base-2, scale prefolded) ----
        const bool diag = (kt == qt);
        float mx0 = -1e30f, mx1 = -1e30f;
#pragma unroll
        for (int nb = 0; nb < 8; nb++) {
            int cc = nb * 8 + koff;
            int kj = kt * 64 + cc;
            bool ok0 = msk[cc] != 0, ok1 = msk[cc + 1] != 0;
            bool a00 = ok0 && (!diag || kj     <= q0);
            bool a01 = ok1 && (!diag || kj + 1 <= q0);
            bool a10 = ok0 && (!diag || kj     <= q1);
            bool a11 = ok1 && (!diag || kj + 1 <= q1);
            S[nb][0] = a00 ? S[nb][0] : -1e30f;
            S[nb][1] = a01 ? S[nb][1] : -1e30f;
            S[nb][2] = a10 ? S[nb][2] : -1e30f;
            S[nb][3] = a11 ? S[nb][3] : -1e30f;
            mx0 = fmaxf(mx0, fmaxf(S[nb][0], S[nb][1]));
            mx1 = fmaxf(mx1, fmaxf(S[nb][2], S[nb][3]));
        }
        mx0 = fmaxf(mx0, __shfl_xor_sync(0xffffffffu, mx0, 1));
        mx0 = fmaxf(mx0, __shfl_xor_sync(0xffffffffu, mx0, 2));
        mx1 = fmaxf(mx1, __shfl_xor_sync(0xffffffffu, mx1, 1));
        mx1 = fmaxf(mx1, __shfl_xor_sync(0xffffffffu, mx1, 2));
        float m0n = fmaxf(m0, mx0), m1n = fmaxf(m1, mx1);
        float corr0 = ex2(m0 - m0n), corr1 = ex2(m1 - m1n);
        m0 = m0n; m1 = m1n;

        uint32_t pa[4][4];
        float sum0 = 0.f, sum1 = 0.f;
#pragma unroll
        for (int nb = 0; nb < 8; nb++) {
            float p00 = ex2(S[nb][0] - m0), p01 = ex2(S[nb][1] - m0);
            float p10 = ex2(S[nb][2] - m1), p11 = ex2(S[nb][3] - m1);
            sum0 += p00 + p01; sum1 += p10 + p11;
            int ksv = nb >> 1, hi = (nb & 1) * 2;
            pa[ksv][hi + 0] = packh2(p00, p01);
            pa[ksv][hi + 1] = packh2(p10, p11);
        }
        l0 = l0 * corr0 + sum0;
        l1 = l1 * corr1 + sum1;
#pragma unroll
        for (int nb = 0; nb < 8; nb++) {
            O[nb][0] *= corr0; O[nb][1] *= corr0;
            O[nb][2] *= corr1; O[nb][3] *= corr1;
        }

        // ---- O += P V (V B-frags via ldmatrix.x4.trans on raw V) ----
#pragma unroll
        for (int ksv = 0; ksv < 4; ksv++) {
#pragma unroll
            for (int nbp = 0; nbp < 4; nbp++) {
                int key = ksv * 16 + (lm & 1) * 8 + lrr;
                int dim = nbp * 16 + (lm >> 1) * 8;
                uint32_t r0, r1, r2, r3;
                ldsm_x4_t(r0, r1, r2, r3, &Vs[key][dim]);
                uint32_t vb0[2] = {r0, r1}, vb1[2] = {r2, r3};
                mma16816(O[2 * nbp],     pa[ksv], vb0);
                mma16816(O[2 * nbp + 1], pa[ksv], vb1);
            }
        }
    }

    // ---- epilogue ----
    l0 += __shfl_xor_sync(0xffffffffu, l0, 1);
    l0 += __shfl_xor_sync(0xffffffffu, l0, 2);
    l1 += __shfl_xor_sync(0xffffffffu, l1, 1);
    l1 += __shfl_xor_sync(0xffffffffu, l1, 2);
    float inv0 = 1.f / l0, inv1 = 1.f / l1;

    char* r0p = dbase + (size_t)(b * SEQ + q0) * 3072 + (size_t)(h * 64 + koff) * 2;
    char* r1p = dbase + (size_t)(b * SEQ + q1) * 3072 + (size_t)(h * 64 + koff) * 2;
#pragma unroll
    for (int nb = 0; nb < 8; nb++) {
        *(uint32_t*)(r0p + nb * 16) = packh2(O[nb][0] * inv0, O[nb][1] * inv0);
        *(uint32_t*)(r1p + nb * 16) = packh2(O[nb][2] * inv1, O[nb][3] * inv1);
    }
}

// ---------------------------------------------------------------------------
// Kernel 3 — HMMA proj GEMM, stripe ownership, ldmatrix fragment loads.
// ---------------------------------------------------------------------------
#define PROJ_SMEM_BYTES (64 * 776 * 2 + 2 * 128 * 40 * 2)

__global__ __launch_bounds__(256)
void proj_hmma_kernel(const char* __restrict__ att_base,
                      const float* __restrict__ W_proj,
                      const float* __restrict__ b_proj,
                      float* __restrict__ out)
{
    extern __shared__ char smem_raw[];
    __half (*ATTs)[776] = (__half(*)[776])smem_raw;
    __half (*Wt)[40]    = (__half(*)[40])(smem_raw + 64 * 776 * 2);

    const int tid  = threadIdx.x;
    const int warp = tid >> 5, lane = tid & 31;
    const int wm = warp & 3, wn = warp >> 2;
    const int lr = lane >> 2;
    const int koff = (lane & 3) * 2;
    const int lm = lane >> 3, lrr = lane & 7;
    const int rowBase = blockIdx.x * 64;

#pragma unroll
    for (int i = 0; i < 24; i++) {
        int idx = tid + i * 256;
        int r = idx / 96, c8 = (idx - r * 96) * 8;
        *(uint4*)&ATTs[r][c8] =
            *(const uint4*)(att_base + (size_t)(rowBase + r) * 3072 + (size_t)c8 * 2);
    }

    float4 w_pre[4];

#define PROJ_LDG(IT, COLB) do {                                                 \
    int k0_ = (IT) * 32;                                                        \
    _Pragma("unroll")                                                           \
    for (int i = 0; i < 4; i++) {                                               \
        int idx = tid + i * 256;                                                \
        int kr = idx >> 5, n4 = (idx & 31) << 2;                                \
        w_pre[i] = *(const float4*)&W_proj[(size_t)(k0_ + kr) * 768 + (COLB) + n4]; \
    }                                                                           \
} while (0)

#define PROJ_STS(BUF) do {                                                      \
    _Pragma("unroll")                                                           \
    for (int i = 0; i < 4; i++) {                                               \
        int idx = tid + i * 256;                                                \
        int kr = idx >> 5, n4 = (idx & 31) << 2;                                \
        Wt[(BUF) * 128 + n4 + 0][kr] = __float2half_rn(w_pre[i].x);             \
        Wt[(BUF) * 128 + n4 + 1][kr] = __float2half_rn(w_pre[i].y);             \
        Wt[(BUF) * 128 + n4 + 2][kr] = __float2half_rn(w_pre[i].z);             \
        Wt[(BUF) * 128 + n4 + 3][kr] = __float2half_rn(w_pre[i].w);             \
    }                                                                           \
} while (0)

    for (int chunk = 0; chunk < 6; ++chunk) {
        const int colBase = chunk * 128;
        float acc[8][4];
#pragma unroll
        for (int nt = 0; nt < 8; nt++)
#pragma unroll
            for (int j = 0; j < 4; j++) acc[nt][j] = 0.f;

        __syncthreads();
        PROJ_LDG(0, colBase);
        PROJ_STS(0);
        __syncthreads();

        for (int it = 0; it < 24; ++it) {
            const int cur = it & 1;
            const bool more = (it + 1 < 24);
            if (more) PROJ_LDG(it + 1, colBase);

#pragma unroll
            for (int kc = 0; kc < 32; kc += 16) {
                int ak = it * 32 + kc;
                uint32_t aa[4];
                {
                    int r = wm * 16 + lrr + ((lane >> 3) & 1) * 8;
                    int c = ak + (lane >> 4) * 8;
                    ldsm_x4(aa[0], aa[1], aa[2], aa[3], &ATTs[r][c]);
                }
#pragma unroll
                for (int nbp = 0; nbp < 4; nbp++) {
                    int n = wn * 64 + nbp * 16 + (lm >> 1) * 8 + lrr;
                    int k = kc + (lm & 1) * 8;
                    uint32_t r0, r1, r2, r3;
                    ldsm_x4(r0, r1, r2, r3, &Wt[cur * 128 + n][k]);
                    uint32_t wb0[2] = {r0, r1}, wb1[2] = {r2, r3};
                    mma16816(acc[2 * nbp],     aa, wb0);
                    mma16816(acc[2 * nbp + 1], aa, wb1);
                }
            }

            if (more) {
                __syncthreads();
                PROJ_STS(1 - cur);
                __syncthreads();
            }
        }

#pragma unroll
        for (int nt = 0; nt < 8; nt++) {
            int gcol = colBase + wn * 64 + nt * 8 + koff;
            float b0 = b_proj[gcol], b1 = b_proj[gcol + 1];
#pragma unroll
            for (int rh = 0; rh < 2; rh++) {
                int row = rowBase + wm * 16 + lr + rh * 8;
                float2 o;
                o.x = acc[nt][rh * 2 + 0] + b0;
                o.y = acc[nt][rh * 2 + 1] + b1;
                *(float2*)&out[(size_t)row * 768 + gcol] = o;
            }
        }
    }
#undef PROJ_LDG
#undef PROJ_STS
}

// ---------------------------------------------------------------------------
extern "C" void kernel_launch(void* const* d_in, const int* in_sizes, int n_in,
                              void* d_out, int out_size)
{
    const float* x      = (const float*)d_in[0];
    const int*   amask  = (const int*)d_in[1];
    const float* W_attn = (const float*)d_in[2];
    const float* b_attn = (const float*)d_in[3];
    const float* W_proj = (const float*)d_in[4];
    const float* b_proj = (const float*)d_in[5];
    float*       out    = (float*)d_out;
    char*        dbase  = (char*)d_out;

    cudaFuncSetAttribute(proj_hmma_kernel,
                         cudaFuncAttributeMaxDynamicSharedMemorySize,
                         PROJ_SMEM_BYTES);

    for (int b = 0; b < BATCH; b++) {
        qkv_hmma_kernel<<<dim3(2304 / 128, SEQ / 128), 256>>>(x, W_attn, b_attn, dbase, b);
        attn_mma_kernel<<<dim3(SEQ / 64, N_HEADS), 128>>>(amask, dbase, b);
    }
    proj_hmma_kernel<<<M_TOT / 64, 256, PROJ_SMEM_BYTES>>>(dbase, W_proj, b_proj, out);
}

// round 13
// speedup vs baseline: 1.7665x; 1.6688x over previous
#include <cuda_runtime.h>
#include <cuda_fp16.h>
#include <cstdint>

#define D_MODEL 768
#define N_HEADS 12
#define BATCH 2
#define SEQ 4096
#define M_TOT 8192
// 1/sqrt(64) * log2(e) folded into Q at GEMM time (softmax done in base-2)
#define QSCALE 0.1803368801f

// ---------------------------------------------------------------------------
// Scratch lives inside d_out (24 MiB), 8192 regions x 3072 B:
//   [ +0,    +1536) : Q fp16 (written by qkv gemm) then ATT fp16 (overwritten
//                     in-place by attn for its own rows/head slice only)
//   [ +1536, +3072) : striped K/V pool (one batch), chunk c = h*4096+t:
//                     addr = (c/6)*3072 + 1536 + (c%6)*256  (K 128B | V 128B)
// ---------------------------------------------------------------------------

__device__ __forceinline__ unsigned packh2(float a, float b) {
    unsigned lo = (unsigned)__half_as_ushort(__float2half_rn(a));
    unsigned hi = (unsigned)__half_as_ushort(__float2half_rn(b));
    return lo | (hi << 16);
}
__device__ __forceinline__ float ex2(float x) {
    float y; asm("ex2.approx.f32 %0, %1;" : "=f"(y) : "f"(x)); return y;
}
__device__ __forceinline__ void mma16816(float* d, const uint32_t* a,
                                         const uint32_t* b) {
    asm volatile(
        "mma.sync.aligned.m16n8k16.row.col.f32.f16.f16.f32 "
        "{%0,%1,%2,%3}, {%4,%5,%6,%7}, {%8,%9}, {%0,%1,%2,%3};"
        : "+f"(d[0]), "+f"(d[1]), "+f"(d[2]), "+f"(d[3])
        : "r"(a[0]), "r"(a[1]), "r"(a[2]), "r"(a[3]), "r"(b[0]), "r"(b[1]));
}
__device__ __forceinline__ void ldsm_x4(uint32_t& r0, uint32_t& r1,
                                        uint32_t& r2, uint32_t& r3,
                                        const void* p) {
    uint32_t addr = (uint32_t)__cvta_generic_to_shared(p);
    asm volatile("ldmatrix.sync.aligned.m8n8.x4.shared.b16 {%0,%1,%2,%3}, [%4];"
                 : "=r"(r0), "=r"(r1), "=r"(r2), "=r"(r3) : "r"(addr));
}
__device__ __forceinline__ void ldsm_x4_t(uint32_t& r0, uint32_t& r1,
                                          uint32_t& r2, uint32_t& r3,
                                          const void* p) {
    uint32_t addr = (uint32_t)__cvta_generic_to_shared(p);
    asm volatile("ldmatrix.sync.aligned.m8n8.x4.trans.shared.b16 {%0,%1,%2,%3}, [%4];"
                 : "=r"(r0), "=r"(r1), "=r"(r2), "=r"(r3) : "r"(addr));
}
__device__ __forceinline__ void cp16(const void* smem, const void* g) {
    uint32_t a = (uint32_t)__cvta_generic_to_shared(smem);
    asm volatile("cp.async.ca.shared.global [%0], [%1], 16;" :: "r"(a), "l"(g));
}
__device__ __forceinline__ void cp4(const void* smem, const void* g) {
    uint32_t a = (uint32_t)__cvta_generic_to_shared(smem);
    asm volatile("cp.async.ca.shared.global [%0], [%1], 4;" :: "r"(a), "l"(g));
}

// ---------------------------------------------------------------------------
// Kernel 1 — HMMA QKV GEMM, double-buffered; W stored raw [k][n] and B-frags
// loaded via ldmatrix.trans (no scalar-STS transpose).
// BM=128, BN=128, BK=32, 256 thr = 8 warps (4m x 2n), warp tile 32x64.
// ---------------------------------------------------------------------------
__global__ __launch_bounds__(256)
void qkv_hmma_kernel(const float* __restrict__ x,
                     const float* __restrict__ W_attn,
                     const float* __restrict__ b_attn,
                     char* __restrict__ dbase, int b)
{
    __shared__ __half As[2][128][40];   // [buf][m][k]
    __shared__ __half Ws[2][32][136];   // [buf][k][n] raw, 8-half pad

    const int tid  = threadIdx.x;
    const int warp = tid >> 5, lane = tid & 31;
    const int wm = warp & 3, wn = warp >> 2;
    const int lr = lane >> 2;
    const int lm = lane >> 3, lrr = lane & 7;
    const int rowBase = blockIdx.y * 128;
    const int colBase = blockIdx.x * 128;
    const float* A = x + (size_t)b * SEQ * D_MODEL;

    float acc[2][8][4];
#pragma unroll
    for (int mt = 0; mt < 2; mt++)
#pragma unroll
        for (int nt = 0; nt < 8; nt++)
#pragma unroll
            for (int j = 0; j < 4; j++) acc[mt][nt][j] = 0.f;

    float4 a_pre[4], w_pre[4];

#define QKV_LDG(IT) do {                                                        \
    int k0_ = (IT) * 32;                                                        \
    _Pragma("unroll")                                                           \
    for (int i = 0; i < 4; i++) {                                               \
        int idx = tid + i * 256;                                                \
        int r = idx >> 3, c4 = (idx & 7) << 2;                                  \
        a_pre[i] = *(const float4*)&A[(size_t)(rowBase + r) * D_MODEL + k0_ + c4]; \
    }                                                                           \
    _Pragma("unroll")                                                           \
    for (int i = 0; i < 4; i++) {                                               \
        int idx = tid + i * 256;                                                \
        int kr = idx >> 5, n4 = (idx & 31) << 2;                                \
        w_pre[i] = *(const float4*)&W_attn[(size_t)(k0_ + kr) * 2304 + colBase + n4]; \
    }                                                                           \
} while (0)

#define QKV_STS(BUF) do {                                                       \
    _Pragma("unroll")                                                           \
    for (int i = 0; i < 4; i++) {                                               \
        int idx = tid + i * 256;                                                \
        int r = idx >> 3, c4 = (idx & 7) << 2;                                  \
        *(uint32_t*)&As[BUF][r][c4]     = packh2(a_pre[i].x, a_pre[i].y);       \
        *(uint32_t*)&As[BUF][r][c4 + 2] = packh2(a_pre[i].z, a_pre[i].w);       \
        int kr = idx >> 5, n4 = (idx & 31) << 2;                                \
        *(uint32_t*)&Ws[BUF][kr][n4]     = packh2(w_pre[i].x, w_pre[i].y);      \
        *(uint32_t*)&Ws[BUF][kr][n4 + 2] = packh2(w_pre[i].z, w_pre[i].w);      \
    }                                                                           \
} while (0)

    QKV_LDG(0);
    QKV_STS(0);
    __syncthreads();

    for (int it = 0; it < 24; ++it) {
        const int cur = it & 1;
        const bool more = (it + 1 < 24);
        if (more) QKV_LDG(it + 1);

#pragma unroll
        for (int kc = 0; kc < 32; kc += 16) {
            uint32_t qa[2][4];
#pragma unroll
            for (int mt = 0; mt < 2; mt++) {
                int r = wm * 32 + mt * 16 + lrr + ((lane >> 3) & 1) * 8;
                int c = kc + (lane >> 4) * 8;
                ldsm_x4(qa[mt][0], qa[mt][1], qa[mt][2], qa[mt][3],
                        &As[cur][r][c]);
            }
#pragma unroll
            for (int nbp = 0; nbp < 4; nbp++) {
                int k = kc + (lm & 1) * 8 + lrr;
                int n = wn * 64 + nbp * 16 + (lm >> 1) * 8;
                uint32_t r0, r1, r2, r3;
                ldsm_x4_t(r0, r1, r2, r3, &Ws[cur][k][n]);
                uint32_t wb0[2] = {r0, r1}, wb1[2] = {r2, r3};
                mma16816(acc[0][2 * nbp],     qa[0], wb0);
                mma16816(acc[0][2 * nbp + 1], qa[0], wb1);
                mma16816(acc[1][2 * nbp],     qa[1], wb0);
                mma16816(acc[1][2 * nbp + 1], qa[1], wb1);
            }
        }

        if (more) {
            __syncthreads();
            QKV_STS(1 - cur);
            __syncthreads();
        }
    }
#undef QKV_LDG
#undef QKV_STS

#pragma unroll
    for (int nt = 0; nt < 8; nt++) {
        int gcol = colBase + wn * 64 + nt * 8 + (lane & 3) * 2;
        int which = gcol / 768;
        int cc = gcol - which * 768;
        int h = cc >> 6, d0 = cc & 63;
        float b0 = b_attn[gcol], b1 = b_attn[gcol + 1];
        float sc = (which == 0) ? QSCALE : 1.f;
#pragma unroll
        for (int mt = 0; mt < 2; mt++) {
#pragma unroll
            for (int rh = 0; rh < 2; rh++) {
                int t = rowBase + wm * 32 + mt * 16 + lr + rh * 8;
                float v0 = (acc[mt][nt][rh * 2 + 0] + b0) * sc;
                float v1 = (acc[mt][nt][rh * 2 + 1] + b1) * sc;
                char* pa;
                if (which == 0) {
                    pa = dbase + (size_t)(b * SEQ + t) * 3072 + (size_t)(h * 64 + d0) * 2;
                } else {
                    int c = h * SEQ + t;
                    int p = c / 6, s = c - p * 6;
                    pa = dbase + (size_t)p * 3072 + 1536 + s * 256
                       + (which == 2 ? 128 : 0) + d0 * 2;
                }
                *(uint32_t*)pa = packh2(v0, v1);
            }
        }
    }
}

// ---------------------------------------------------------------------------
// Kernel 2 — tensor-core flash attention: R10/R12 shape (64-row tile, 128 thr,
// 4 blocks/SM) + cp.async double-buffered K/V + incremental pool addressing
// (no per-tile integer division) + rescale skip when max didn't move.
// Static smem: Qs 9216 + Ks/Vs 2x9216x2 + msk 512 = 46592 B (< 48K static cap).
// ---------------------------------------------------------------------------
__global__ __launch_bounds__(128, 4)
void attn_mma_kernel(const int* __restrict__ attn_mask,
                     char* __restrict__ dbase, int b)
{
    const int qt   = (int)gridDim.x - 1 - (int)blockIdx.x;  // heavy first
    const int h    = blockIdx.y;
    const int tid  = threadIdx.x;
    const int warp = tid >> 5, lane = tid & 31;
    const int lr   = lane >> 2;
    const int koff = (lane & 3) * 2;
    const int lm = lane >> 3, lrr = lane & 7;

    __shared__ __half Qs[64][72];
    __shared__ __half Ks[2][64][72];
    __shared__ __half Vs[2][64][72];     // raw [key][dim]
    __shared__ int    msk2[2][64];

    // ---- stage Q tile ----
#pragma unroll
    for (int i = 0; i < 4; i++) {
        int idx = tid + i * 128;
        int rr = idx >> 3, c8 = (idx & 7) * 8;
        const char* src = dbase + (size_t)(b * SEQ + qt * 64 + rr) * 3072
                        + (size_t)(h * 64 + c8) * 2;
        *(uint4*)&Qs[rr][c8] = *(const uint4*)src;
    }
    __syncthreads();

    uint32_t qa[4][4];
    const int qr = warp * 16 + lr;
    {
        int r = warp * 16 + lrr + ((lane >> 3) & 1) * 8;
#pragma unroll
        for (int ks = 0; ks < 4; ks++) {
            int c = ks * 16 + (lane >> 4) * 8;
            ldsm_x4(qa[ks][0], qa[ks][1], qa[ks][2], qa[ks][3], &Qs[r][c]);
        }
    }

    const int q0 = qt * 64 + qr;
    const int q1 = q0 + 8;

    float m0 = -1e30f, m1 = -1e30f, l0 = 0.f, l1 = 0.f;
    float O[8][4];
#pragma unroll
    for (int nb = 0; nb < 8; nb++)
#pragma unroll
        for (int j = 0; j < 4; j++) O[nb][j] = 0.f;

    // ---- incremental pool addressing state (advance by 64 keys per tile:
    //      64 = 6*10 + 4  ->  p += 10, s += 4, wrap at 6) ----
    int pp[4], ss[4];
#pragma unroll
    for (int i = 0; i < 4; i++) {
        int rr = (tid + i * 128) >> 3;
        int c0 = h * SEQ + rr;
        pp[i] = c0 / 6;
        ss[i] = c0 - pp[i] * 6;
    }
    const int* mptr = attn_mask + b * SEQ + tid;   // used by tid<64 only

#define ATT_STAGE(BUF) do {                                                     \
    _Pragma("unroll")                                                           \
    for (int i = 0; i < 4; i++) {                                               \
        int idx = tid + i * 128;                                                \
        int rr = idx >> 3, c8 = (idx & 7) * 8;                                  \
        const char* base = dbase + (size_t)pp[i] * 3072 + 1536 + ss[i] * 256;   \
        cp16(&Ks[BUF][rr][c8], base + c8 * 2);                                  \
        cp16(&Vs[BUF][rr][c8], base + 128 + c8 * 2);                            \
        pp[i] += 10; ss[i] += 4;                                                \
        if (ss[i] >= 6) { ss[i] -= 6; pp[i] += 1; }                             \
    }                                                                           \
    if (tid < 64) cp4(&msk2[BUF][tid], mptr);                                   \
    mptr += 64;                                                                 \
    asm volatile("cp.async.commit_group;");                                     \
} while (0)

    ATT_STAGE(0);

    for (int kt = 0; kt <= qt; kt++) {
        const int cur = kt & 1;
        __syncthreads();                        // buffer 1-cur free to restage
        if (kt < qt) {
            ATT_STAGE(1 - cur);
            asm volatile("cp.async.wait_group 1;");
        } else {
            asm volatile("cp.async.wait_group 0;");
        }
        __syncthreads();

        // ---- S = Q K^T ----
        float S[8][4];
#pragma unroll
        for (int nb = 0; nb < 8; nb++)
#pragma unroll
            for (int j = 0; j < 4; j++) S[nb][j] = 0.f;

#pragma unroll
        for (int ks = 0; ks < 4; ks++) {
#pragma unroll
            for (int nbp = 0; nbp < 4; nbp++) {
                int n = nbp * 16 + (lm >> 1) * 8 + lrr;
                int k = ks * 16 + (lm & 1) * 8;
                uint32_t r0, r1, r2, r3;
                ldsm_x4(r0, r1, r2, r3, &Ks[cur][n][k]);
                uint32_t kb0[2] = {r0, r1}, kb1[2] = {r2, r3};
                mma16816(S[2 * nbp],     qa[ks], kb0);
                mma16816(S[2 * nbp + 1], qa[ks], kb1);
            }
        }

        // ---- mask + online softmax (base-2, scale prefolded) ----
        const bool diag = (kt == qt);
        const int* mk = msk2[cur];
        float mx0 = -1e30f, mx1 = -1e30f;
#pragma unroll
        for (int nb = 0; nb < 8; nb++) {
            int cc = nb * 8 + koff;
            int kj = kt * 64 + cc;
            bool ok0 = mk[cc] != 0, ok1 = mk[cc + 1] != 0;
            bool a00 = ok0 && (!diag || kj     <= q0);
            bool a01 = ok1 && (!diag || kj + 1 <= q0);
            bool a10 = ok0 && (!diag || kj     <= q1);
            bool a11 = ok1 && (!diag || kj + 1 <= q1);
            S[nb][0] = a00 ? S[nb][0] : -1e30f;
            S[nb][1] = a01 ? S[nb][1] : -1e30f;
            S[nb][2] = a10 ? S[nb][2] : -1e30f;
            S[nb][3] = a11 ? S[nb][3] : -1e30f;
            mx0 = fmaxf(mx0, fmaxf(S[nb][0], S[nb][1]));
            mx1 = fmaxf(mx1, fmaxf(S[nb][2], S[nb][3]));
        }
        mx0 = fmaxf(mx0, __shfl_xor_sync(0xffffffffu, mx0, 1));
        mx0 = fmaxf(mx0, __shfl_xor_sync(0xffffffffu, mx0, 2));
        mx1 = fmaxf(mx1, __shfl_xor_sync(0xffffffffu, mx1, 1));
        mx1 = fmaxf(mx1, __shfl_xor_sync(0xffffffffu, mx1, 2));
        float m0n = fmaxf(m0, mx0), m1n = fmaxf(m1, mx1);
        const bool nochange =
            __all_sync(0xffffffffu, (m0n == m0) && (m1n == m1));
        float corr0 = ex2(m0 - m0n), corr1 = ex2(m1 - m1n);
        m0 = m0n; m1 = m1n;

        uint32_t pa[4][4];
        float sum0 = 0.f, sum1 = 0.f;
#pragma unroll
        for (int nb = 0; nb < 8; nb++) {
            float p00 = ex2(S[nb][0] - m0), p01 = ex2(S[nb][1] - m0);
            float p10 = ex2(S[nb][2] - m1), p11 = ex2(S[nb][3] - m1);
            sum0 += p00 + p01; sum1 += p10 + p11;
            int ksv = nb >> 1, hi = (nb & 1) * 2;
            pa[ksv][hi + 0] = packh2(p00, p01);
            pa[ksv][hi + 1] = packh2(p10, p11);
        }
        l0 = l0 * corr0 + sum0;
        l1 = l1 * corr1 + sum1;
        if (!nochange) {
#pragma unroll
            for (int nb = 0; nb < 8; nb++) {
                O[nb][0] *= corr0; O[nb][1] *= corr0;
                O[nb][2] *= corr1; O[nb][3] *= corr1;
            }
        }

        // ---- O += P V (V B-frags via ldmatrix.x4.trans on raw V) ----
#pragma unroll
        for (int ksv = 0; ksv < 4; ksv++) {
#pragma unroll
            for (int nbp = 0; nbp < 4; nbp++) {
                int key = ksv * 16 + (lm & 1) * 8 + lrr;
                int dim = nbp * 16 + (lm >> 1) * 8;
                uint32_t r0, r1, r2, r3;
                ldsm_x4_t(r0, r1, r2, r3, &Vs[cur][key][dim]);
                uint32_t vb0[2] = {r0, r1}, vb1[2] = {r2, r3};
                mma16816(O[2 * nbp],     pa[ksv], vb0);
                mma16816(O[2 * nbp + 1], pa[ksv], vb1);
            }
        }
    }
#undef ATT_STAGE

    // ---- epilogue ----
    l0 += __shfl_xor_sync(0xffffffffu, l0, 1);
    l0 += __shfl_xor_sync(0xffffffffu, l0, 2);
    l1 += __shfl_xor_sync(0xffffffffu, l1, 1);
    l1 += __shfl_xor_sync(0xffffffffu, l1, 2);
    float inv0 = 1.f / l0, inv1 = 1.f / l1;

    char* r0p = dbase + (size_t)(b * SEQ + q0) * 3072 + (size_t)(h * 64 + koff) * 2;
    char* r1p = dbase + (size_t)(b * SEQ + q1) * 3072 + (size_t)(h * 64 + koff) * 2;
#pragma unroll
    for (int nb = 0; nb < 8; nb++) {
        *(uint32_t*)(r0p + nb * 16) = packh2(O[nb][0] * inv0, O[nb][1] * inv0);
        *(uint32_t*)(r1p + nb * 16) = packh2(O[nb][2] * inv1, O[nb][3] * inv1);
    }
}

// ---------------------------------------------------------------------------
// Kernel 3 — HMMA proj GEMM, stripe ownership; W raw [k][n] + ldmatrix.trans.
// Dynamic smem: ATTs 64x776x2 (99328) + Ws 2x32x136x2 (17408) = 116736 B.
// ---------------------------------------------------------------------------
#define PROJ_SMEM_BYTES (64 * 776 * 2 + 2 * 32 * 136 * 2)

__global__ __launch_bounds__(256)
void proj_hmma_kernel(const char* __restrict__ att_base,
                      const float* __restrict__ W_proj,
                      const float* __restrict__ b_proj,
                      float* __restrict__ out)
{
    extern __shared__ char smem_raw[];
    __half (*ATTs)[776] = (__half(*)[776])smem_raw;
    __half (*Ws)[136]   = (__half(*)[136])(smem_raw + 64 * 776 * 2); // [buf*32+k][n]

    const int tid  = threadIdx.x;
    const int warp = tid >> 5, lane = tid & 31;
    const int wm = warp & 3, wn = warp >> 2;
    const int lr = lane >> 2;
    const int koff = (lane & 3) * 2;
    const int lm = lane >> 3, lrr = lane & 7;
    const int rowBase = blockIdx.x * 64;

#pragma unroll
    for (int i = 0; i < 24; i++) {
        int idx = tid + i * 256;
        int r = idx / 96, c8 = (idx - r * 96) * 8;
        *(uint4*)&ATTs[r][c8] =
            *(const uint4*)(att_base + (size_t)(rowBase + r) * 3072 + (size_t)c8 * 2);
    }

    float4 w_pre[4];

#define PROJ_LDG(IT, COLB) do {                                                 \
    int k0_ = (IT) * 32;                                                        \
    _Pragma("unroll")                                                           \
    for (int i = 0; i < 4; i++) {                                               \
        int idx = tid + i * 256;                                                \
        int kr = idx >> 5, n4 = (idx & 31) << 2;                                \
        w_pre[i] = *(const float4*)&W_proj[(size_t)(k0_ + kr) * 768 + (COLB) + n4]; \
    }                                                                           \
} while (0)

#define PROJ_STS(BUF) do {                                                      \
    _Pragma("unroll")                                                           \
    for (int i = 0; i < 4; i++) {                                               \
        int idx = tid + i * 256;                                                \
        int kr = idx >> 5, n4 = (idx & 31) << 2;                                \
        *(uint32_t*)&Ws[(BUF) * 32 + kr][n4]     = packh2(w_pre[i].x, w_pre[i].y); \
        *(uint32_t*)&Ws[(BUF) * 32 + kr][n4 + 2] = packh2(w_pre[i].z, w_pre[i].w); \
    }                                                                           \
} while (0)

    for (int chunk = 0; chunk < 6; ++chunk) {
        const int colBase = chunk * 128;
        float acc[8][4];
#pragma unroll
        for (int nt = 0; nt < 8; nt++)
#pragma unroll
            for (int j = 0; j < 4; j++) acc[nt][j] = 0.f;

        __syncthreads();
        PROJ_LDG(0, colBase);
        PROJ_STS(0);
        __syncthreads();

        for (int it = 0; it < 24; ++it) {
            const int cur = it & 1;
            const bool more = (it + 1 < 24);
            if (more) PROJ_LDG(it + 1, colBase);

#pragma unroll
            for (int kc = 0; kc < 32; kc += 16) {
                int ak = it * 32 + kc;
                uint32_t aa[4];
                {
                    int r = wm * 16 + lrr + ((lane >> 3) & 1) * 8;
                    int c = ak + (lane >> 4) * 8;
                    ldsm_x4(aa[0], aa[1], aa[2], aa[3], &ATTs[r][c]);
                }
#pragma unroll
                for (int nbp = 0; nbp < 4; nbp++) {
                    int k = kc + (lm & 1) * 8 + lrr;
                    int n = wn * 64 + nbp * 16 + (lm >> 1) * 8;
                    uint32_t r0, r1, r2, r3;
                    ldsm_x4_t(r0, r1, r2, r3, &Ws[cur * 32 + k][n]);
                    uint32_t wb0[2] = {r0, r1}, wb1[2] = {r2, r3};
                    mma16816(acc[2 * nbp],     aa, wb0);
                    mma16816(acc[2 * nbp + 1], aa, wb1);
                }
            }

            if (more) {
                __syncthreads();
                PROJ_STS(1 - cur);
                __syncthreads();
            }
        }

#pragma unroll
        for (int nt = 0; nt < 8; nt++) {
            int gcol = colBase + wn * 64 + nt * 8 + koff;
            float b0 = b_proj[gcol], b1 = b_proj[gcol + 1];
#pragma unroll
            for (int rh = 0; rh < 2; rh++) {
                int row = rowBase + wm * 16 + lr + rh * 8;
                float2 o;
                o.x = acc[nt][rh * 2 + 0] + b0;
                o.y = acc[nt][rh * 2 + 1] + b1;
                *(float2*)&out[(size_t)row * 768 + gcol] = o;
            }
        }
    }
#undef PROJ_LDG
#undef PROJ_STS
}

// ---------------------------------------------------------------------------
extern "C" void kernel_launch(void* const* d_in, const int* in_sizes, int n_in,
                              void* d_out, int out_size)
{
    const float* x      = (const float*)d_in[0];
    const int*   amask  = (const int*)d_in[1];
    const float* W_attn = (const float*)d_in[2];
    const float* b_attn = (const float*)d_in[3];
    const float* W_proj = (const float*)d_in[4];
    const float* b_proj = (const float*)d_in[5];
    float*       out    = (float*)d_out;
    char*        dbase  = (char*)d_out;

    cudaFuncSetAttribute(proj_hmma_kernel,
                         cudaFuncAttributeMaxDynamicSharedMemorySize,
                         PROJ_SMEM_BYTES);

    for (int b = 0; b < BATCH; b++) {
        qkv_hmma_kernel<<<dim3(2304 / 128, SEQ / 128), 256>>>(x, W_attn, b_attn, dbase, b);
        attn_mma_kernel<<<dim3(SEQ / 64, N_HEADS), 128>>>(amask, dbase, b);
    }
    proj_hmma_kernel<<<M_TOT / 64, 256, PROJ_SMEM_BYTES>>>(dbase, W_proj, b_proj, out);
}

// round 14
// speedup vs baseline: 2.0467x; 1.1586x over previous
#include <cuda_runtime.h>
#include <cuda_fp16.h>
#include <cstdint>

#define D_MODEL 768
#define N_HEADS 12
#define BATCH 2
#define SEQ 4096
#define M_TOT 8192
// 1/sqrt(64) * log2(e) folded into Q at GEMM time (softmax done in base-2)
#define QSCALE 0.1803368801f

// ---------------------------------------------------------------------------
// Scratch lives inside d_out (24 MiB), 8192 regions x 3072 B:
//   [ +0,    +1536) : Q fp16 (written by qkv gemm) then ATT fp16 (overwritten
//                     in-place by attn for its own rows/head slice only)
//   [ +1536, +3072) : striped K/V pool (one batch), chunk c = h*4096+t:
//                     addr = (c/6)*3072 + 1536 + (c%6)*256  (K 128B | V 128B)
// ---------------------------------------------------------------------------

__device__ __forceinline__ unsigned packh2(float a, float b) {
    // d = {lo=a, hi=b}; cvt.rn.f16x2.f32 d, x, y -> hi=cvt(x), lo=cvt(y)
    unsigned r;
    asm("cvt.rn.f16x2.f32 %0, %1, %2;" : "=r"(r) : "f"(b), "f"(a));
    return r;
}
__device__ __forceinline__ unsigned hex2h2(unsigned x) {
    unsigned y; asm("ex2.approx.f16x2 %0, %1;" : "=r"(y) : "r"(x)); return y;
}
__device__ __forceinline__ float ex2(float x) {
    float y; asm("ex2.approx.f32 %0, %1;" : "=f"(y) : "f"(x)); return y;
}
__device__ __forceinline__ void mma16816(float* d, const uint32_t* a,
                                         const uint32_t* b) {
    asm volatile(
        "mma.sync.aligned.m16n8k16.row.col.f32.f16.f16.f32 "
        "{%0,%1,%2,%3}, {%4,%5,%6,%7}, {%8,%9}, {%0,%1,%2,%3};"
        : "+f"(d[0]), "+f"(d[1]), "+f"(d[2]), "+f"(d[3])
        : "r"(a[0]), "r"(a[1]), "r"(a[2]), "r"(a[3]), "r"(b[0]), "r"(b[1]));
}
__device__ __forceinline__ void ldsm_x4(uint32_t& r0, uint32_t& r1,
                                        uint32_t& r2, uint32_t& r3,
                                        const void* p) {
    uint32_t addr = (uint32_t)__cvta_generic_to_shared(p);
    asm volatile("ldmatrix.sync.aligned.m8n8.x4.shared.b16 {%0,%1,%2,%3}, [%4];"
                 : "=r"(r0), "=r"(r1), "=r"(r2), "=r"(r3) : "r"(addr));
}
__device__ __forceinline__ void ldsm_x4_t(uint32_t& r0, uint32_t& r1,
                                          uint32_t& r2, uint32_t& r3,
                                          const void* p) {
    uint32_t addr = (uint32_t)__cvta_generic_to_shared(p);
    asm volatile("ldmatrix.sync.aligned.m8n8.x4.trans.shared.b16 {%0,%1,%2,%3}, [%4];"
                 : "=r"(r0), "=r"(r1), "=r"(r2), "=r"(r3) : "r"(addr));
}
__device__ __forceinline__ void cp16(const void* smem, const void* g) {
    uint32_t a = (uint32_t)__cvta_generic_to_shared(smem);
    asm volatile("cp.async.ca.shared.global [%0], [%1], 16;" :: "r"(a), "l"(g));
}
__device__ __forceinline__ void cp4(const void* smem, const void* g) {
    uint32_t a = (uint32_t)__cvta_generic_to_shared(smem);
    asm volatile("cp.async.ca.shared.global [%0], [%1], 4;" :: "r"(a), "l"(g));
}

// ---------------------------------------------------------------------------
// Kernel 1 — HMMA QKV GEMM (unchanged from R13).
// ---------------------------------------------------------------------------
__global__ __launch_bounds__(256)
void qkv_hmma_kernel(const float* __restrict__ x,
                     const float* __restrict__ W_attn,
                     const float* __restrict__ b_attn,
                     char* __restrict__ dbase, int b)
{
    __shared__ __half As[2][128][40];   // [buf][m][k]
    __shared__ __half Ws[2][32][136];   // [buf][k][n] raw, 8-half pad

    const int tid  = threadIdx.x;
    const int warp = tid >> 5, lane = tid & 31;
    const int wm = warp & 3, wn = warp >> 2;
    const int lr = lane >> 2;
    const int lm = lane >> 3, lrr = lane & 7;
    const int rowBase = blockIdx.y * 128;
    const int colBase = blockIdx.x * 128;
    const float* A = x + (size_t)b * SEQ * D_MODEL;

    float acc[2][8][4];
#pragma unroll
    for (int mt = 0; mt < 2; mt++)
#pragma unroll
        for (int nt = 0; nt < 8; nt++)
#pragma unroll
            for (int j = 0; j < 4; j++) acc[mt][nt][j] = 0.f;

    float4 a_pre[4], w_pre[4];

#define QKV_LDG(IT) do {                                                        \
    int k0_ = (IT) * 32;                                                        \
    _Pragma("unroll")                                                           \
    for (int i = 0; i < 4; i++) {                                               \
        int idx = tid + i * 256;                                                \
        int r = idx >> 3, c4 = (idx & 7) << 2;                                  \
        a_pre[i] = *(const float4*)&A[(size_t)(rowBase + r) * D_MODEL + k0_ + c4]; \
    }                                                                           \
    _Pragma("unroll")                                                           \
    for (int i = 0; i < 4; i++) {                                               \
        int idx = tid + i * 256;                                                \
        int kr = idx >> 5, n4 = (idx & 31) << 2;                                \
        w_pre[i] = *(const float4*)&W_attn[(size_t)(k0_ + kr) * 2304 + colBase + n4]; \
    }                                                                           \
} while (0)

#define QKV_STS(BUF) do {                                                       \
    _Pragma("unroll")                                                           \
    for (int i = 0; i < 4; i++) {                                               \
        int idx = tid + i * 256;                                                \
        int r = idx >> 3, c4 = (idx & 7) << 2;                                  \
        *(uint32_t*)&As[BUF][r][c4]     = packh2(a_pre[i].x, a_pre[i].y);       \
        *(uint32_t*)&As[BUF][r][c4 + 2] = packh2(a_pre[i].z, a_pre[i].w);       \
        int kr = idx >> 5, n4 = (idx & 31) << 2;                                \
        *(uint32_t*)&Ws[BUF][kr][n4]     = packh2(w_pre[i].x, w_pre[i].y);      \
        *(uint32_t*)&Ws[BUF][kr][n4 + 2] = packh2(w_pre[i].z, w_pre[i].w);      \
    }                                                                           \
} while (0)

    QKV_LDG(0);
    QKV_STS(0);
    __syncthreads();

    for (int it = 0; it < 24; ++it) {
        const int cur = it & 1;
        const bool more = (it + 1 < 24);
        if (more) QKV_LDG(it + 1);

#pragma unroll
        for (int kc = 0; kc < 32; kc += 16) {
            uint32_t qa[2][4];
#pragma unroll
            for (int mt = 0; mt < 2; mt++) {
                int r = wm * 32 + mt * 16 + lrr + ((lane >> 3) & 1) * 8;
                int c = kc + (lane >> 4) * 8;
                ldsm_x4(qa[mt][0], qa[mt][1], qa[mt][2], qa[mt][3],
                        &As[cur][r][c]);
            }
#pragma unroll
            for (int nbp = 0; nbp < 4; nbp++) {
                int k = kc + (lm & 1) * 8 + lrr;
                int n = wn * 64 + nbp * 16 + (lm >> 1) * 8;
                uint32_t r0, r1, r2, r3;
                ldsm_x4_t(r0, r1, r2, r3, &Ws[cur][k][n]);
                uint32_t wb0[2] = {r0, r1}, wb1[2] = {r2, r3};
                mma16816(acc[0][2 * nbp],     qa[0], wb0);
                mma16816(acc[0][2 * nbp + 1], qa[0], wb1);
                mma16816(acc[1][2 * nbp],     qa[1], wb0);
                mma16816(acc[1][2 * nbp + 1], qa[1], wb1);
            }
        }

        if (more) {
            __syncthreads();
            QKV_STS(1 - cur);
            __syncthreads();
        }
    }
#undef QKV_LDG
#undef QKV_STS

#pragma unroll
    for (int nt = 0; nt < 8; nt++) {
        int gcol = colBase + wn * 64 + nt * 8 + (lane & 3) * 2;
        int which = gcol / 768;
        int cc = gcol - which * 768;
        int h = cc >> 6, d0 = cc & 63;
        float b0 = b_attn[gcol], b1 = b_attn[gcol + 1];
        float sc = (which == 0) ? QSCALE : 1.f;
#pragma unroll
        for (int mt = 0; mt < 2; mt++) {
#pragma unroll
            for (int rh = 0; rh < 2; rh++) {
                int t = rowBase + wm * 32 + mt * 16 + lr + rh * 8;
                float v0 = (acc[mt][nt][rh * 2 + 0] + b0) * sc;
                float v1 = (acc[mt][nt][rh * 2 + 1] + b1) * sc;
                char* pa;
                if (which == 0) {
                    pa = dbase + (size_t)(b * SEQ + t) * 3072 + (size_t)(h * 64 + d0) * 2;
                } else {
                    int c = h * SEQ + t;
                    int p = c / 6, s = c - p * 6;
                    pa = dbase + (size_t)p * 3072 + 1536 + s * 256
                       + (which == 2 ? 128 : 0) + d0 * 2;
                }
                *(uint32_t*)pa = packh2(v0, v1);
            }
        }
    }
}

// ---------------------------------------------------------------------------
// Kernel 2 — tensor-core flash attention: R13 pipeline + (a) per-tile mask
// validity flags (skip masking on interior valid tiles), (b) softmax exp in
// ex2.approx.f16x2 directly into the PV A-fragment, (c) l via P@ones MMA.
// ---------------------------------------------------------------------------
__global__ __launch_bounds__(128, 4)
void attn_mma_kernel(const int* __restrict__ attn_mask,
                     char* __restrict__ dbase, int b)
{
    const int qt   = (int)gridDim.x - 1 - (int)blockIdx.x;  // heavy first
    const int h    = blockIdx.y;
    const int tid  = threadIdx.x;
    const int warp = tid >> 5, lane = tid & 31;
    const int lr   = lane >> 2;
    const int koff = (lane & 3) * 2;
    const int lm = lane >> 3, lrr = lane & 7;

    __shared__ __half Qs[64][72];
    __shared__ __half Ks[2][64][72];
    __shared__ __half Vs[2][64][72];     // raw [key][dim]
    __shared__ int    msk2[2][64];
    __shared__ int    tflag[64];         // per-key-tile "mask all valid"

    // ---- stage Q tile + precompute mask-tile validity flags ----
#pragma unroll
    for (int i = 0; i < 4; i++) {
        int idx = tid + i * 128;
        int rr = idx >> 3, c8 = (idx & 7) * 8;
        const char* src = dbase + (size_t)(b * SEQ + qt * 64 + rr) * 3072
                        + (size_t)(h * 64 + c8) * 2;
        *(uint4*)&Qs[rr][c8] = *(const uint4*)src;
    }
    if (tid < 64 && tid <= qt) {
        const int4* mrow = (const int4*)(attn_mask + b * SEQ + tid * 64);
        int all = 1;
#pragma unroll
        for (int i = 0; i < 16; i++) {
            int4 v = mrow[i];
            all &= (v.x && v.y && v.z && v.w) ? 1 : 0;
        }
        tflag[tid] = all;
    }
    __syncthreads();

    uint32_t qa[4][4];
    const int qr = warp * 16 + lr;
    {
        int r = warp * 16 + lrr + ((lane >> 3) & 1) * 8;
#pragma unroll
        for (int ks = 0; ks < 4; ks++) {
            int c = ks * 16 + (lane >> 4) * 8;
            ldsm_x4(qa[ks][0], qa[ks][1], qa[ks][2], qa[ks][3], &Qs[r][c]);
        }
    }

    const int q0 = qt * 64 + qr;
    const int q1 = q0 + 8;

    float m0 = -1e30f, m1 = -1e30f;
    float O[8][4];
    float lacc[4] = {0.f, 0.f, 0.f, 0.f};   // l via P@ones MMA
    const uint32_t onesb[2] = {0x3C003C00u, 0x3C003C00u};
#pragma unroll
    for (int nb = 0; nb < 8; nb++)
#pragma unroll
        for (int j = 0; j < 4; j++) O[nb][j] = 0.f;

    // ---- incremental pool addressing (advance 64 keys: p+=10, s+=4 wrap 6) ----
    int pp[4], ss[4];
#pragma unroll
    for (int i = 0; i < 4; i++) {
        int rr = (tid + i * 128) >> 3;
        int c0 = h * SEQ + rr;
        pp[i] = c0 / 6;
        ss[i] = c0 - pp[i] * 6;
    }
    const int* mptr = attn_mask + b * SEQ + tid;   // used by tid<64 only

#define ATT_STAGE(BUF) do {                                                     \
    _Pragma("unroll")                                                           \
    for (int i = 0; i < 4; i++) {                                               \
        int idx = tid + i * 128;                                                \
        int rr = idx >> 3, c8 = (idx & 7) * 8;                                  \
        const char* base = dbase + (size_t)pp[i] * 3072 + 1536 + ss[i] * 256;   \
        cp16(&Ks[BUF][rr][c8], base + c8 * 2);                                  \
        cp16(&Vs[BUF][rr][c8], base + 128 + c8 * 2);                            \
        pp[i] += 10; ss[i] += 4;                                                \
        if (ss[i] >= 6) { ss[i] -= 6; pp[i] += 1; }                             \
    }                                                                           \
    if (tid < 64) cp4(&msk2[BUF][tid], mptr);                                   \
    mptr += 64;                                                                 \
    asm volatile("cp.async.commit_group;");                                     \
} while (0)

    ATT_STAGE(0);

    for (int kt = 0; kt <= qt; kt++) {
        const int cur = kt & 1;
        __syncthreads();                        // buffer 1-cur free to restage
        if (kt < qt) {
            ATT_STAGE(1 - cur);
            asm volatile("cp.async.wait_group 1;");
        } else {
            asm volatile("cp.async.wait_group 0;");
        }
        __syncthreads();

        // ---- S = Q K^T ----
        float S[8][4];
#pragma unroll
        for (int nb = 0; nb < 8; nb++)
#pragma unroll
            for (int j = 0; j < 4; j++) S[nb][j] = 0.f;

#pragma unroll
        for (int ks = 0; ks < 4; ks++) {
#pragma unroll
            for (int nbp = 0; nbp < 4; nbp++) {
                int n = nbp * 16 + (lm >> 1) * 8 + lrr;
                int k = ks * 16 + (lm & 1) * 8;
                uint32_t r0, r1, r2, r3;
                ldsm_x4(r0, r1, r2, r3, &Ks[cur][n][k]);
                uint32_t kb0[2] = {r0, r1}, kb1[2] = {r2, r3};
                mma16816(S[2 * nbp],     qa[ks], kb0);
                mma16816(S[2 * nbp + 1], qa[ks], kb1);
            }
        }

        // ---- masking: only when the diagonal tile or an invalid mask tile ----
        const bool diag = (kt == qt);
        const bool allv = (tflag[kt] != 0);
        if (diag || !allv) {
            const int* mk = msk2[cur];
#pragma unroll
            for (int nb = 0; nb < 8; nb++) {
                int cc = nb * 8 + koff;
                int kj = kt * 64 + cc;
                bool ok0 = allv || (mk[cc] != 0);
                bool ok1 = allv || (mk[cc + 1] != 0);
                bool a00 = ok0 && (!diag || kj     <= q0);
                bool a01 = ok1 && (!diag || kj + 1 <= q0);
                bool a10 = ok0 && (!diag || kj     <= q1);
                bool a11 = ok1 && (!diag || kj + 1 <= q1);
                S[nb][0] = a00 ? S[nb][0] : -1e30f;
                S[nb][1] = a01 ? S[nb][1] : -1e30f;
                S[nb][2] = a10 ? S[nb][2] : -1e30f;
                S[nb][3] = a11 ? S[nb][3] : -1e30f;
            }
        }

        // ---- online softmax (base-2, scale prefolded) ----
        float mx0 = -1e30f, mx1 = -1e30f;
#pragma unroll
        for (int nb = 0; nb < 8; nb++) {
            mx0 = fmaxf(mx0, fmaxf(S[nb][0], S[nb][1]));
            mx1 = fmaxf(mx1, fmaxf(S[nb][2], S[nb][3]));
        }
        mx0 = fmaxf(mx0, __shfl_xor_sync(0xffffffffu, mx0, 1));
        mx0 = fmaxf(mx0, __shfl_xor_sync(0xffffffffu, mx0, 2));
        mx1 = fmaxf(mx1, __shfl_xor_sync(0xffffffffu, mx1, 1));
        mx1 = fmaxf(mx1, __shfl_xor_sync(0xffffffffu, mx1, 2));
        float m0n = fmaxf(m0, mx0), m1n = fmaxf(m1, mx1);
        const bool nochange =
            __all_sync(0xffffffffu, (m0n == m0) && (m1n == m1));
        float corr0 = ex2(m0 - m0n), corr1 = ex2(m1 - m1n);
        m0 = m0n; m1 = m1n;

        // p = 2^(S-m) computed directly in f16x2 -> PV A-fragments
        uint32_t pa[4][4];
#pragma unroll
        for (int nb = 0; nb < 8; nb++) {
            int ksv = nb >> 1, hi = (nb & 1) * 2;
            pa[ksv][hi + 0] = hex2h2(packh2(S[nb][0] - m0, S[nb][1] - m0));
            pa[ksv][hi + 1] = hex2h2(packh2(S[nb][2] - m1, S[nb][3] - m1));
        }
        if (!nochange) {
#pragma unroll
            for (int nb = 0; nb < 8; nb++) {
                O[nb][0] *= corr0; O[nb][1] *= corr0;
                O[nb][2] *= corr1; O[nb][3] *= corr1;
            }
            lacc[0] *= corr0; lacc[1] *= corr0;
            lacc[2] *= corr1; lacc[3] *= corr1;
        }

        // ---- O += P V ; l += P @ ones ----
#pragma unroll
        for (int ksv = 0; ksv < 4; ksv++) {
            mma16816(lacc, pa[ksv], onesb);
#pragma unroll
            for (int nbp = 0; nbp < 4; nbp++) {
                int key = ksv * 16 + (lm & 1) * 8 + lrr;
                int dim = nbp * 16 + (lm >> 1) * 8;
                uint32_t r0, r1, r2, r3;
                ldsm_x4_t(r0, r1, r2, r3, &Vs[cur][key][dim]);
                uint32_t vb0[2] = {r0, r1}, vb1[2] = {r2, r3};
                mma16816(O[2 * nbp],     pa[ksv], vb0);
                mma16816(O[2 * nbp + 1], pa[ksv], vb1);
            }
        }
    }
#undef ATT_STAGE

    // ---- epilogue (l already fully reduced by the ones-MMA) ----
    float inv0 = 1.f / lacc[0], inv1 = 1.f / lacc[2];

    char* r0p = dbase + (size_t)(b * SEQ + q0) * 3072 + (size_t)(h * 64 + koff) * 2;
    char* r1p = dbase + (size_t)(b * SEQ + q1) * 3072 + (size_t)(h * 64 + koff) * 2;
#pragma unroll
    for (int nb = 0; nb < 8; nb++) {
        *(uint32_t*)(r0p + nb * 16) = packh2(O[nb][0] * inv0, O[nb][1] * inv0);
        *(uint32_t*)(r1p + nb * 16) = packh2(O[nb][2] * inv1, O[nb][3] * inv1);
    }
}

// ---------------------------------------------------------------------------
// Kernel 3 — HMMA proj GEMM (unchanged from R13).
// ---------------------------------------------------------------------------
#define PROJ_SMEM_BYTES (64 * 776 * 2 + 2 * 32 * 136 * 2)

__global__ __launch_bounds__(256)
void proj_hmma_kernel(const char* __restrict__ att_base,
                      const float* __restrict__ W_proj,
                      const float* __restrict__ b_proj,
                      float* __restrict__ out)
{
    extern __shared__ char smem_raw[];
    __half (*ATTs)[776] = (__half(*)[776])smem_raw;
    __half (*Ws)[136]   = (__half(*)[136])(smem_raw + 64 * 776 * 2);

    const int tid  = threadIdx.x;
    const int warp = tid >> 5, lane = tid & 31;
    const int wm = warp & 3, wn = warp >> 2;
    const int lr = lane >> 2;
    const int koff = (lane & 3) * 2;
    const int lm = lane >> 3, lrr = lane & 7;
    const int rowBase = blockIdx.x * 64;

#pragma unroll
    for (int i = 0; i < 24; i++) {
        int idx = tid + i * 256;
        int r = idx / 96, c8 = (idx - r * 96) * 8;
        *(uint4*)&ATTs[r][c8] =
            *(const uint4*)(att_base + (size_t)(rowBase + r) * 3072 + (size_t)c8 * 2);
    }

    float4 w_pre[4];

#define PROJ_LDG(IT, COLB) do {                                                 \
    int k0_ = (IT) * 32;                                                        \
    _Pragma("unroll")                                                           \
    for (int i = 0; i < 4; i++) {                                               \
        int idx = tid + i * 256;                                                \
        int kr = idx >> 5, n4 = (idx & 31) << 2;                                \
        w_pre[i] = *(const float4*)&W_proj[(size_t)(k0_ + kr) * 768 + (COLB) + n4]; \
    }                                                                           \
} while (0)

#define PROJ_STS(BUF) do {                                                      \
    _Pragma("unroll")                                                           \
    for (int i = 0; i < 4; i++) {                                               \
        int idx = tid + i * 256;                                                \
        int kr = idx >> 5, n4 = (idx & 31) << 2;                                \
        *(uint32_t*)&Ws[(BUF) * 32 + kr][n4]     = packh2(w_pre[i].x, w_pre[i].y); \
        *(uint32_t*)&Ws[(BUF) * 32 + kr][n4 + 2] = packh2(w_pre[i].z, w_pre[i].w); \
    }                                                                           \
} while (0)

    for (int chunk = 0; chunk < 6; ++chunk) {
        const int colBase = chunk * 128;
        float acc[8][4];
#pragma unroll
        for (int nt = 0; nt < 8; nt++)
#pragma unroll
            for (int j = 0; j < 4; j++) acc[nt][j] = 0.f;

        __syncthreads();
        PROJ_LDG(0, colBase);
        PROJ_STS(0);
        __syncthreads();

        for (int it = 0; it < 24; ++it) {
            const int cur = it & 1;
            const bool more = (it + 1 < 24);
            if (more) PROJ_LDG(it + 1, colBase);

#pragma unroll
            for (int kc = 0; kc < 32; kc += 16) {
                int ak = it * 32 + kc;
                uint32_t aa[4];
                {
                    int r = wm * 16 + lrr + ((lane >> 3) & 1) * 8;
                    int c = ak + (lane >> 4) * 8;
                    ldsm_x4(aa[0], aa[1], aa[2], aa[3], &ATTs[r][c]);
                }
#pragma unroll
                for (int nbp = 0; nbp < 4; nbp++) {
                    int k = kc + (lm & 1) * 8 + lrr;
                    int n = wn * 64 + nbp * 16 + (lm >> 1) * 8;
                    uint32_t r0, r1, r2, r3;
                    ldsm_x4_t(r0, r1, r2, r3, &Ws[cur * 32 + k][n]);
                    uint32_t wb0[2] = {r0, r1}, wb1[2] = {r2, r3};
                    mma16816(acc[2 * nbp],     aa, wb0);
                    mma16816(acc[2 * nbp + 1], aa, wb1);
                }
            }

            if (more) {
                __syncthreads();
                PROJ_STS(1 - cur);
                __syncthreads();
            }
        }

#pragma unroll
        for (int nt = 0; nt < 8; nt++) {
            int gcol = colBase + wn * 64 + nt * 8 + koff;
            float b0 = b_proj[gcol], b1 = b_proj[gcol + 1];
#pragma unroll
            for (int rh = 0; rh < 2; rh++) {
                int row = rowBase + wm * 16 + lr + rh * 8;
                float2 o;
                o.x = acc[nt][rh * 2 + 0] + b0;
                o.y = acc[nt][rh * 2 + 1] + b1;
                *(float2*)&out[(size_t)row * 768 + gcol] = o;
            }
        }
    }
#undef PROJ_LDG
#undef PROJ_STS
}

// ---------------------------------------------------------------------------
extern "C" void kernel_launch(void* const* d_in, const int* in_sizes, int n_in,
                              void* d_out, int out_size)
{
    const float* x      = (const float*)d_in[0];
    const int*   amask  = (const int*)d_in[1];
    const float* W_attn = (const float*)d_in[2];
    const float* b_attn = (const float*)d_in[3];
    const float* W_proj = (const float*)d_in[4];
    const float* b_proj = (const float*)d_in[5];
    float*       out    = (float*)d_out;
    char*        dbase  = (char*)d_out;

    cudaFuncSetAttribute(proj_hmma_kernel,
                         cudaFuncAttributeMaxDynamicSharedMemorySize,
                         PROJ_SMEM_BYTES);

    for (int b = 0; b < BATCH; b++) {
        qkv_hmma_kernel<<<dim3(2304 / 128, SEQ / 128), 256>>>(x, W_attn, b_attn, dbase, b);
        attn_mma_kernel<<<dim3(SEQ / 64, N_HEADS), 128>>>(amask, dbase, b);
    }
    proj_hmma_kernel<<<M_TOT / 64, 256, PROJ_SMEM_BYTES>>>(dbase, W_proj, b_proj, out);
}

// round 15
// speedup vs baseline: 2.0510x; 1.0021x over previous
#include <cuda_runtime.h>
#include <cuda_fp16.h>
#include <cstdint>

#define D_MODEL 768
#define N_HEADS 12
#define BATCH 2
#define SEQ 4096
#define M_TOT 8192
// 1/sqrt(64) * log2(e) folded into Q at GEMM time (softmax done in base-2)
#define QSCALE 0.1803368801f

// ---------------------------------------------------------------------------
// Scratch lives inside d_out (24 MiB), 8192 regions x 3072 B:
//   [ +0,    +1536) : Q fp16 (written by qkv gemm) then ATT fp16 (overwritten
//                     in-place by attn for its own rows/head slice only)
//   [ +1536, +3072) : striped K/V pool (one batch), chunk c = h*4096+t:
//                     addr = (c/6)*3072 + 1536 + (c%6)*256  (K 128B | V 128B)
// ---------------------------------------------------------------------------

__device__ __forceinline__ unsigned packh2(float a, float b) {
    unsigned r;
    asm("cvt.rn.f16x2.f32 %0, %1, %2;" : "=r"(r) : "f"(b), "f"(a));
    return r;
}
__device__ __forceinline__ unsigned hex2h2(unsigned x) {
    unsigned y; asm("ex2.approx.f16x2 %0, %1;" : "=r"(y) : "r"(x)); return y;
}
__device__ __forceinline__ float ex2(float x) {
    float y; asm("ex2.approx.f32 %0, %1;" : "=f"(y) : "f"(x)); return y;
}
__device__ __forceinline__ void mma16816(float* d, const uint32_t* a,
                                         const uint32_t* b) {
    asm volatile(
        "mma.sync.aligned.m16n8k16.row.col.f32.f16.f16.f32 "
        "{%0,%1,%2,%3}, {%4,%5,%6,%7}, {%8,%9}, {%0,%1,%2,%3};"
        : "+f"(d[0]), "+f"(d[1]), "+f"(d[2]), "+f"(d[3])
        : "r"(a[0]), "r"(a[1]), "r"(a[2]), "r"(a[3]), "r"(b[0]), "r"(b[1]));
}
// Zero-C variant: C operands are constant 0.0 (ptxas -> RZ); D is write-only.
// Removes the need to pre-zero accumulator fragments.
__device__ __forceinline__ void mma16816_zc(float* d, const uint32_t* a,
                                            const uint32_t* b) {
    asm volatile(
        "mma.sync.aligned.m16n8k16.row.col.f32.f16.f16.f32 "
        "{%0,%1,%2,%3}, {%4,%5,%6,%7}, {%8,%9}, {%10,%10,%10,%10};"
        : "=f"(d[0]), "=f"(d[1]), "=f"(d[2]), "=f"(d[3])
        : "r"(a[0]), "r"(a[1]), "r"(a[2]), "r"(a[3]), "r"(b[0]), "r"(b[1]),
          "f"(0.f));
}
__device__ __forceinline__ void ldsm_x4(uint32_t& r0, uint32_t& r1,
                                        uint32_t& r2, uint32_t& r3,
                                        const void* p) {
    uint32_t addr = (uint32_t)__cvta_generic_to_shared(p);
    asm volatile("ldmatrix.sync.aligned.m8n8.x4.shared.b16 {%0,%1,%2,%3}, [%4];"
                 : "=r"(r0), "=r"(r1), "=r"(r2), "=r"(r3) : "r"(addr));
}
__device__ __forceinline__ void ldsm_x4_t(uint32_t& r0, uint32_t& r1,
                                          uint32_t& r2, uint32_t& r3,
                                          const void* p) {
    uint32_t addr = (uint32_t)__cvta_generic_to_shared(p);
    asm volatile("ldmatrix.sync.aligned.m8n8.x4.trans.shared.b16 {%0,%1,%2,%3}, [%4];"
                 : "=r"(r0), "=r"(r1), "=r"(r2), "=r"(r3) : "r"(addr));
}
__device__ __forceinline__ void cp16(const void* smem, const void* g) {
    uint32_t a = (uint32_t)__cvta_generic_to_shared(smem);
    asm volatile("cp.async.ca.shared.global [%0], [%1], 16;" :: "r"(a), "l"(g));
}
__device__ __forceinline__ void cp4(const void* smem, const void* g) {
    uint32_t a = (uint32_t)__cvta_generic_to_shared(smem);
    asm volatile("cp.async.ca.shared.global [%0], [%1], 4;" :: "r"(a), "l"(g));
}

// ---------------------------------------------------------------------------
// Kernel 1 — HMMA QKV GEMM (unchanged from R13/R14).
// ---------------------------------------------------------------------------
__global__ __launch_bounds__(256)
void qkv_hmma_kernel(const float* __restrict__ x,
                     const float* __restrict__ W_attn,
                     const float* __restrict__ b_attn,
                     char* __restrict__ dbase, int b)
{
    __shared__ __half As[2][128][40];   // [buf][m][k]
    __shared__ __half Ws[2][32][136];   // [buf][k][n] raw, 8-half pad

    const int tid  = threadIdx.x;
    const int warp = tid >> 5, lane = tid & 31;
    const int wm = warp & 3, wn = warp >> 2;
    const int lr = lane >> 2;
    const int lm = lane >> 3, lrr = lane & 7;
    const int rowBase = blockIdx.y * 128;
    const int colBase = blockIdx.x * 128;
    const float* A = x + (size_t)b * SEQ * D_MODEL;

    float acc[2][8][4];
#pragma unroll
    for (int mt = 0; mt < 2; mt++)
#pragma unroll
        for (int nt = 0; nt < 8; nt++)
#pragma unroll
            for (int j = 0; j < 4; j++) acc[mt][nt][j] = 0.f;

    float4 a_pre[4], w_pre[4];

#define QKV_LDG(IT) do {                                                        \
    int k0_ = (IT) * 32;                                                        \
    _Pragma("unroll")                                                           \
    for (int i = 0; i < 4; i++) {                                               \
        int idx = tid + i * 256;                                                \
        int r = idx >> 3, c4 = (idx & 7) << 2;                                  \
        a_pre[i] = *(const float4*)&A[(size_t)(rowBase + r) * D_MODEL + k0_ + c4]; \
    }                                                                           \
    _Pragma("unroll")                                                           \
    for (int i = 0; i < 4; i++) {                                               \
        int idx = tid + i * 256;                                                \
        int kr = idx >> 5, n4 = (idx & 31) << 2;                                \
        w_pre[i] = *(const float4*)&W_attn[(size_t)(k0_ + kr) * 2304 + colBase + n4]; \
    }                                                                           \
} while (0)

#define QKV_STS(BUF) do {                                                       \
    _Pragma("unroll")                                                           \
    for (int i = 0; i < 4; i++) {                                               \
        int idx = tid + i * 256;                                                \
        int r = idx >> 3, c4 = (idx & 7) << 2;                                  \
        *(uint32_t*)&As[BUF][r][c4]     = packh2(a_pre[i].x, a_pre[i].y);       \
        *(uint32_t*)&As[BUF][r][c4 + 2] = packh2(a_pre[i].z, a_pre[i].w);       \
        int kr = idx >> 5, n4 = (idx & 31) << 2;                                \
        *(uint32_t*)&Ws[BUF][kr][n4]     = packh2(w_pre[i].x, w_pre[i].y);      \
        *(uint32_t*)&Ws[BUF][kr][n4 + 2] = packh2(w_pre[i].z, w_pre[i].w);      \
    }                                                                           \
} while (0)

    QKV_LDG(0);
    QKV_STS(0);
    __syncthreads();

    for (int it = 0; it < 24; ++it) {
        const int cur = it & 1;
        const bool more = (it + 1 < 24);
        if (more) QKV_LDG(it + 1);

#pragma unroll
        for (int kc = 0; kc < 32; kc += 16) {
            uint32_t qa[2][4];
#pragma unroll
            for (int mt = 0; mt < 2; mt++) {
                int r = wm * 32 + mt * 16 + lrr + ((lane >> 3) & 1) * 8;
                int c = kc + (lane >> 4) * 8;
                ldsm_x4(qa[mt][0], qa[mt][1], qa[mt][2], qa[mt][3],
                        &As[cur][r][c]);
            }
#pragma unroll
            for (int nbp = 0; nbp < 4; nbp++) {
                int k = kc + (lm & 1) * 8 + lrr;
                int n = wn * 64 + nbp * 16 + (lm >> 1) * 8;
                uint32_t r0, r1, r2, r3;
                ldsm_x4_t(r0, r1, r2, r3, &Ws[cur][k][n]);
                uint32_t wb0[2] = {r0, r1}, wb1[2] = {r2, r3};
                mma16816(acc[0][2 * nbp],     qa[0], wb0);
                mma16816(acc[0][2 * nbp + 1], qa[0], wb1);
                mma16816(acc[1][2 * nbp],     qa[1], wb0);
                mma16816(acc[1][2 * nbp + 1], qa[1], wb1);
            }
        }

        if (more) {
            __syncthreads();
            QKV_STS(1 - cur);
            __syncthreads();
        }
    }
#undef QKV_LDG
#undef QKV_STS

#pragma unroll
    for (int nt = 0; nt < 8; nt++) {
        int gcol = colBase + wn * 64 + nt * 8 + (lane & 3) * 2;
        int which = gcol / 768;
        int cc = gcol - which * 768;
        int h = cc >> 6, d0 = cc & 63;
        float b0 = b_attn[gcol], b1 = b_attn[gcol + 1];
        float sc = (which == 0) ? QSCALE : 1.f;
#pragma unroll
        for (int mt = 0; mt < 2; mt++) {
#pragma unroll
            for (int rh = 0; rh < 2; rh++) {
                int t = rowBase + wm * 32 + mt * 16 + lr + rh * 8;
                float v0 = (acc[mt][nt][rh * 2 + 0] + b0) * sc;
                float v1 = (acc[mt][nt][rh * 2 + 1] + b1) * sc;
                char* pa;
                if (which == 0) {
                    pa = dbase + (size_t)(b * SEQ + t) * 3072 + (size_t)(h * 64 + d0) * 2;
                } else {
                    int c = h * SEQ + t;
                    int p = c / 6, s = c - p * 6;
                    pa = dbase + (size_t)p * 3072 + 1536 + s * 256
                       + (which == 2 ? 128 : 0) + d0 * 2;
                }
                *(uint32_t*)pa = packh2(v0, v1);
            }
        }
    }
}

// ---------------------------------------------------------------------------
// Kernel 2 — tensor-core flash attention: R14 + zero-C MMA for S (no per-tile
// accumulator zeroing; first k-step writes S with C=RZ).
// ---------------------------------------------------------------------------
__global__ __launch_bounds__(128, 4)
void attn_mma_kernel(const int* __restrict__ attn_mask,
                     char* __restrict__ dbase, int b)
{
    const int qt   = (int)gridDim.x - 1 - (int)blockIdx.x;  // heavy first
    const int h    = blockIdx.y;
    const int tid  = threadIdx.x;
    const int warp = tid >> 5, lane = tid & 31;
    const int lr   = lane >> 2;
    const int koff = (lane & 3) * 2;
    const int lm = lane >> 3, lrr = lane & 7;

    __shared__ __half Qs[64][72];
    __shared__ __half Ks[2][64][72];
    __shared__ __half Vs[2][64][72];     // raw [key][dim]
    __shared__ int    msk2[2][64];
    __shared__ int    tflag[64];         // per-key-tile "mask all valid"

    // ---- stage Q tile + precompute mask-tile validity flags ----
#pragma unroll
    for (int i = 0; i < 4; i++) {
        int idx = tid + i * 128;
        int rr = idx >> 3, c8 = (idx & 7) * 8;
        const char* src = dbase + (size_t)(b * SEQ + qt * 64 + rr) * 3072
                        + (size_t)(h * 64 + c8) * 2;
        *(uint4*)&Qs[rr][c8] = *(const uint4*)src;
    }
    if (tid < 64 && tid <= qt) {
        const int4* mrow = (const int4*)(attn_mask + b * SEQ + tid * 64);
        int all = 1;
#pragma unroll
        for (int i = 0; i < 16; i++) {
            int4 v = mrow[i];
            all &= (v.x && v.y && v.z && v.w) ? 1 : 0;
        }
        tflag[tid] = all;
    }
    __syncthreads();

    uint32_t qa[4][4];
    const int qr = warp * 16 + lr;
    {
        int r = warp * 16 + lrr + ((lane >> 3) & 1) * 8;
#pragma unroll
        for (int ks = 0; ks < 4; ks++) {
            int c = ks * 16 + (lane >> 4) * 8;
            ldsm_x4(qa[ks][0], qa[ks][1], qa[ks][2], qa[ks][3], &Qs[r][c]);
        }
    }

    const int q0 = qt * 64 + qr;
    const int q1 = q0 + 8;

    float m0 = -1e30f, m1 = -1e30f;
    float O[8][4];
    float lacc[4] = {0.f, 0.f, 0.f, 0.f};   // l via P@ones MMA
    const uint32_t onesb[2] = {0x3C003C00u, 0x3C003C00u};
#pragma unroll
    for (int nb = 0; nb < 8; nb++)
#pragma unroll
        for (int j = 0; j < 4; j++) O[nb][j] = 0.f;

    // ---- incremental pool addressing (advance 64 keys: p+=10, s+=4 wrap 6) ----
    int pp[4], ss[4];
#pragma unroll
    for (int i = 0; i < 4; i++) {
        int rr = (tid + i * 128) >> 3;
        int c0 = h * SEQ + rr;
        pp[i] = c0 / 6;
        ss[i] = c0 - pp[i] * 6;
    }
    const int* mptr = attn_mask + b * SEQ + tid;   // used by tid<64 only

#define ATT_STAGE(BUF) do {                                                     \
    _Pragma("unroll")                                                           \
    for (int i = 0; i < 4; i++) {                                               \
        int idx = tid + i * 128;                                                \
        int rr = idx >> 3, c8 = (idx & 7) * 8;                                  \
        const char* base = dbase + (size_t)pp[i] * 3072 + 1536 + ss[i] * 256;   \
        cp16(&Ks[BUF][rr][c8], base + c8 * 2);                                  \
        cp16(&Vs[BUF][rr][c8], base + 128 + c8 * 2);                            \
        pp[i] += 10; ss[i] += 4;                                                \
        if (ss[i] >= 6) { ss[i] -= 6; pp[i] += 1; }                             \
    }                                                                           \
    if (tid < 64) cp4(&msk2[BUF][tid], mptr);                                   \
    mptr += 64;                                                                 \
    asm volatile("cp.async.commit_group;");                                     \
} while (0)

    ATT_STAGE(0);

    for (int kt = 0; kt <= qt; kt++) {
        const int cur = kt & 1;
        __syncthreads();                        // buffer 1-cur free to restage
        if (kt < qt) {
            ATT_STAGE(1 - cur);
            asm volatile("cp.async.wait_group 1;");
        } else {
            asm volatile("cp.async.wait_group 0;");
        }
        __syncthreads();

        // ---- S = Q K^T (ks=0 writes S with zero-C; ks=1..3 accumulate) ----
        float S[8][4];
#pragma unroll
        for (int nbp = 0; nbp < 4; nbp++) {
            int n = nbp * 16 + (lm >> 1) * 8 + lrr;
            int k = (lm & 1) * 8;
            uint32_t r0, r1, r2, r3;
            ldsm_x4(r0, r1, r2, r3, &Ks[cur][n][k]);
            uint32_t kb0[2] = {r0, r1}, kb1[2] = {r2, r3};
            mma16816_zc(S[2 * nbp],     qa[0], kb0);
            mma16816_zc(S[2 * nbp + 1], qa[0], kb1);
        }
#pragma unroll
        for (int ks = 1; ks < 4; ks++) {
#pragma unroll
            for (int nbp = 0; nbp < 4; nbp++) {
                int n = nbp * 16 + (lm >> 1) * 8 + lrr;
                int k = ks * 16 + (lm & 1) * 8;
                uint32_t r0, r1, r2, r3;
                ldsm_x4(r0, r1, r2, r3, &Ks[cur][n][k]);
                uint32_t kb0[2] = {r0, r1}, kb1[2] = {r2, r3};
                mma16816(S[2 * nbp],     qa[ks], kb0);
                mma16816(S[2 * nbp + 1], qa[ks], kb1);
            }
        }

        // ---- masking: only the diagonal tile or an invalid mask tile ----
        const bool diag = (kt == qt);
        const bool allv = (tflag[kt] != 0);
        if (diag || !allv) {
            const int* mk = msk2[cur];
#pragma unroll
            for (int nb = 0; nb < 8; nb++) {
                int cc = nb * 8 + koff;
                int kj = kt * 64 + cc;
                bool ok0 = allv || (mk[cc] != 0);
                bool ok1 = allv || (mk[cc + 1] != 0);
                bool a00 = ok0 && (!diag || kj     <= q0);
                bool a01 = ok1 && (!diag || kj + 1 <= q0);
                bool a10 = ok0 && (!diag || kj     <= q1);
                bool a11 = ok1 && (!diag || kj + 1 <= q1);
                S[nb][0] = a00 ? S[nb][0] : -1e30f;
                S[nb][1] = a01 ? S[nb][1] : -1e30f;
                S[nb][2] = a10 ? S[nb][2] : -1e30f;
                S[nb][3] = a11 ? S[nb][3] : -1e30f;
            }
        }

        // ---- online softmax (base-2, scale prefolded) ----
        float mx0 = -1e30f, mx1 = -1e30f;
#pragma unroll
        for (int nb = 0; nb < 8; nb++) {
            mx0 = fmaxf(mx0, fmaxf(S[nb][0], S[nb][1]));
            mx1 = fmaxf(mx1, fmaxf(S[nb][2], S[nb][3]));
        }
        mx0 = fmaxf(mx0, __shfl_xor_sync(0xffffffffu, mx0, 1));
        mx0 = fmaxf(mx0, __shfl_xor_sync(0xffffffffu, mx0, 2));
        mx1 = fmaxf(mx1, __shfl_xor_sync(0xffffffffu, mx1, 1));
        mx1 = fmaxf(mx1, __shfl_xor_sync(0xffffffffu, mx1, 2));
        float m0n = fmaxf(m0, mx0), m1n = fmaxf(m1, mx1);
        const bool nochange =
            __all_sync(0xffffffffu, (m0n == m0) && (m1n == m1));
        float corr0 = ex2(m0 - m0n), corr1 = ex2(m1 - m1n);
        m0 = m0n; m1 = m1n;

        // p = 2^(S-m) computed directly in f16x2 -> PV A-fragments
        uint32_t pa[4][4];
#pragma unroll
        for (int nb = 0; nb < 8; nb++) {
            int ksv = nb >> 1, hi = (nb & 1) * 2;
            pa[ksv][hi + 0] = hex2h2(packh2(S[nb][0] - m0, S[nb][1] - m0));
            pa[ksv][hi + 1] = hex2h2(packh2(S[nb][2] - m1, S[nb][3] - m1));
        }
        if (!nochange) {
#pragma unroll
            for (int nb = 0; nb < 8; nb++) {
                O[nb][0] *= corr0; O[nb][1] *= corr0;
                O[nb][2] *= corr1; O[nb][3] *= corr1;
            }
            lacc[0] *= corr0;           // lacc[1] mirrors lacc[0] (ones-B),
            lacc[2] *= corr1;           // lacc[3] mirrors lacc[2]; only the
        }                               // used lanes need rescaling.

        // ---- O += P V ; l += P @ ones ----
#pragma unroll
        for (int ksv = 0; ksv < 4; ksv++) {
            mma16816(lacc, pa[ksv], onesb);
#pragma unroll
            for (int nbp = 0; nbp < 4; nbp++) {
                int key = ksv * 16 + (lm & 1) * 8 + lrr;
                int dim = nbp * 16 + (lm >> 1) * 8;
                uint32_t r0, r1, r2, r3;
                ldsm_x4_t(r0, r1, r2, r3, &Vs[cur][key][dim]);
                uint32_t vb0[2] = {r0, r1}, vb1[2] = {r2, r3};
                mma16816(O[2 * nbp],     pa[ksv], vb0);
                mma16816(O[2 * nbp + 1], pa[ksv], vb1);
            }
        }
    }
#undef ATT_STAGE

    // ---- epilogue (l already fully reduced by the ones-MMA) ----
    float inv0 = 1.f / lacc[0], inv1 = 1.f / lacc[2];

    char* r0p = dbase + (size_t)(b * SEQ + q0) * 3072 + (size_t)(h * 64 + koff) * 2;
    char* r1p = dbase + (size_t)(b * SEQ + q1) * 3072 + (size_t)(h * 64 + koff) * 2;
#pragma unroll
    for (int nb = 0; nb < 8; nb++) {
        *(uint32_t*)(r0p + nb * 16) = packh2(O[nb][0] * inv0, O[nb][1] * inv0);
        *(uint32_t*)(r1p + nb * 16) = packh2(O[nb][2] * inv1, O[nb][3] * inv1);
    }
}

// ---------------------------------------------------------------------------
// Kernel 3 — HMMA proj GEMM (unchanged from R13/R14).
// ---------------------------------------------------------------------------
#define PROJ_SMEM_BYTES (64 * 776 * 2 + 2 * 32 * 136 * 2)

__global__ __launch_bounds__(256)
void proj_hmma_kernel(const char* __restrict__ att_base,
                      const float* __restrict__ W_proj,
                      const float* __restrict__ b_proj,
                      float* __restrict__ out)
{
    extern __shared__ char smem_raw[];
    __half (*ATTs)[776] = (__half(*)[776])smem_raw;
    __half (*Ws)[136]   = (__half(*)[136])(smem_raw + 64 * 776 * 2);

    const int tid  = threadIdx.x;
    const int warp = tid >> 5, lane = tid & 31;
    const int wm = warp & 3, wn = warp >> 2;
    const int lr = lane >> 2;
    const int koff = (lane & 3) * 2;
    const int lm = lane >> 3, lrr = lane & 7;
    const int rowBase = blockIdx.x * 64;

#pragma unroll
    for (int i = 0; i < 24; i++) {
        int idx = tid + i * 256;
        int r = idx / 96, c8 = (idx - r * 96) * 8;
        *(uint4*)&ATTs[r][c8] =
            *(const uint4*)(att_base + (size_t)(rowBase + r) * 3072 + (size_t)c8 * 2);
    }

    float4 w_pre[4];

#define PROJ_LDG(IT, COLB) do {                                                 \
    int k0_ = (IT) * 32;                                                        \
    _Pragma("unroll")                                                           \
    for (int i = 0; i < 4; i++) {                                               \
        int idx = tid + i * 256;                                                \
        int kr = idx >> 5, n4 = (idx & 31) << 2;                                \
        w_pre[i] = *(const float4*)&W_proj[(size_t)(k0_ + kr) * 768 + (COLB) + n4]; \
    }                                                                           \
} while (0)

#define PROJ_STS(BUF) do {                                                      \
    _Pragma("unroll")                                                           \
    for (int i = 0; i < 4; i++) {                                               \
        int idx = tid + i * 256;                                                \
        int kr = idx >> 5, n4 = (idx & 31) << 2;                                \
        *(uint32_t*)&Ws[(BUF) * 32 + kr][n4]     = packh2(w_pre[i].x, w_pre[i].y); \
        *(uint32_t*)&Ws[(BUF) * 32 + kr][n4 + 2] = packh2(w_pre[i].z, w_pre[i].w); \
    }                                                                           \
} while (0)

    for (int chunk = 0; chunk < 6; ++chunk) {
        const int colBase = chunk * 128;
        float acc[8][4];
#pragma unroll
        for (int nt = 0; nt < 8; nt++)
#pragma unroll
            for (int j = 0; j < 4; j++) acc[nt][j] = 0.f;

        __syncthreads();
        PROJ_LDG(0, colBase);
        PROJ_STS(0);
        __syncthreads();

        for (int it = 0; it < 24; ++it) {
            const int cur = it & 1;
            const bool more = (it + 1 < 24);
            if (more) PROJ_LDG(it + 1, colBase);

#pragma unroll
            for (int kc = 0; kc < 32; kc += 16) {
                int ak = it * 32 + kc;
                uint32_t aa[4];
                {
                    int r = wm * 16 + lrr + ((lane >> 3) & 1) * 8;
                    int c = ak + (lane >> 4) * 8;
                    ldsm_x4(aa[0], aa[1], aa[2], aa[3], &ATTs[r][c]);
                }
#pragma unroll
                for (int nbp = 0; nbp < 4; nbp++) {
                    int k = kc + (lm & 1) * 8 + lrr;
                    int n = wn * 64 + nbp * 16 + (lm >> 1) * 8;
                    uint32_t r0, r1, r2, r3;
                    ldsm_x4_t(r0, r1, r2, r3, &Ws[cur * 32 + k][n]);
                    uint32_t wb0[2] = {r0, r1}, wb1[2] = {r2, r3};
                    mma16816(acc[2 * nbp],     aa, wb0);
                    mma16816(acc[2 * nbp + 1], aa, wb1);
                }
            }

            if (more) {
                __syncthreads();
                PROJ_STS(1 - cur);
                __syncthreads();
            }
        }

#pragma unroll
        for (int nt = 0; nt < 8; nt++) {
            int gcol = colBase + wn * 64 + nt * 8 + koff;
            float b0 = b_proj[gcol], b1 = b_proj[gcol + 1];
#pragma unroll
            for (int rh = 0; rh < 2; rh++) {
                int row = rowBase + wm * 16 + lr + rh * 8;
                float2 o;
                o.x = acc[nt][rh * 2 + 0] + b0;
                o.y = acc[nt][rh * 2 + 1] + b1;
                *(float2*)&out[(size_t)row * 768 + gcol] = o;
            }
        }
    }
#undef PROJ_LDG
#undef PROJ_STS
}

// ---------------------------------------------------------------------------
extern "C" void kernel_launch(void* const* d_in, const int* in_sizes, int n_in,
                              void* d_out, int out_size)
{
    const float* x      = (const float*)d_in[0];
    const int*   amask  = (const int*)d_in[1];
    const float* W_attn = (const float*)d_in[2];
    const float* b_attn = (const float*)d_in[3];
    const float* W_proj = (const float*)d_in[4];
    const float* b_proj = (const float*)d_in[5];
    float*       out    = (float*)d_out;
    char*        dbase  = (char*)d_out;

    cudaFuncSetAttribute(proj_hmma_kernel,
                         cudaFuncAttributeMaxDynamicSharedMemorySize,
                         PROJ_SMEM_BYTES);

    for (int b = 0; b < BATCH; b++) {
        qkv_hmma_kernel<<<dim3(2304 / 128, SEQ / 128), 256>>>(x, W_attn, b_attn, dbase, b);
        attn_mma_kernel<<<dim3(SEQ / 64, N_HEADS), 128>>>(amask, dbase, b);
    }
    proj_hmma_kernel<<<M_TOT / 64, 256, PROJ_SMEM_BYTES>>>(dbase, W_proj, b_proj, out);
}

// round 16
// speedup vs baseline: 2.1089x; 1.0282x over previous
#include <cuda_runtime.h>
#include <cuda_fp16.h>
#include <cstdint>

#define D_MODEL 768
#define N_HEADS 12
#define BATCH 2
#define SEQ 4096
#define M_TOT 8192
// 1/sqrt(64) * log2(e) folded into Q at GEMM time (softmax done in base-2)
#define QSCALE 0.1803368801f

// ---------------------------------------------------------------------------
// Scratch lives inside d_out (24 MiB), 8192 regions x 3072 B:
//   [ +0,    +1536) : Q fp16 (written by qkv gemm) then ATT fp16 (overwritten
//                     in-place by attn for its own rows/head slice only)
//   [ +1536, +3072) : striped K/V pool (one batch), chunk c = h*4096+t:
//                     addr = (c/6)*3072 + 1536 + (c%6)*256  (K 128B | V 128B)
// ---------------------------------------------------------------------------

__device__ __forceinline__ unsigned packh2(float a, float b) {
    unsigned r;
    asm("cvt.rn.f16x2.f32 %0, %1, %2;" : "=r"(r) : "f"(b), "f"(a));
    return r;
}
__device__ __forceinline__ unsigned hex2h2(unsigned x) {
    unsigned y; asm("ex2.approx.f16x2 %0, %1;" : "=r"(y) : "r"(x)); return y;
}
__device__ __forceinline__ unsigned hmax2(unsigned a, unsigned b) {
    unsigned y; asm("max.f16x2 %0, %1, %2;" : "=r"(y) : "r"(a), "r"(b)); return y;
}
__device__ __forceinline__ unsigned hsub2(unsigned a, unsigned b) {
    unsigned y; asm("sub.f16x2 %0, %1, %2;" : "=r"(y) : "r"(a), "r"(b)); return y;
}
__device__ __forceinline__ float h2f_lo(unsigned x) {
    float f;
    asm("{.reg .b16 l, h; mov.b32 {l, h}, %1; cvt.f32.f16 %0, l;}" : "=f"(f) : "r"(x));
    return f;
}
__device__ __forceinline__ float h2f_hi(unsigned x) {
    float f;
    asm("{.reg .b16 l, h; mov.b32 {l, h}, %1; cvt.f32.f16 %0, h;}" : "=f"(f) : "r"(x));
    return f;
}
__device__ __forceinline__ float ex2(float x) {
    float y; asm("ex2.approx.f32 %0, %1;" : "=f"(y) : "f"(x)); return y;
}
__device__ __forceinline__ void mma16816(float* d, const uint32_t* a,
                                         const uint32_t* b) {
    asm volatile(
        "mma.sync.aligned.m16n8k16.row.col.f32.f16.f16.f32 "
        "{%0,%1,%2,%3}, {%4,%5,%6,%7}, {%8,%9}, {%0,%1,%2,%3};"
        : "+f"(d[0]), "+f"(d[1]), "+f"(d[2]), "+f"(d[3])
        : "r"(a[0]), "r"(a[1]), "r"(a[2]), "r"(a[3]), "r"(b[0]), "r"(b[1]));
}
// fp16-accumulate MMA: D,C are f16x2 pairs (2 regs). Zero-C variant writes D.
__device__ __forceinline__ void mma16816_h_zc(uint32_t* d, const uint32_t* a,
                                              const uint32_t* b) {
    asm volatile(
        "mma.sync.aligned.m16n8k16.row.col.f16.f16.f16.f16 "
        "{%0,%1}, {%2,%3,%4,%5}, {%6,%7}, {%8,%8};"
        : "=r"(d[0]), "=r"(d[1])
        : "r"(a[0]), "r"(a[1]), "r"(a[2]), "r"(a[3]), "r"(b[0]), "r"(b[1]),
          "r"(0u));
}
__device__ __forceinline__ void mma16816_h(uint32_t* d, const uint32_t* a,
                                           const uint32_t* b) {
    asm volatile(
        "mma.sync.aligned.m16n8k16.row.col.f16.f16.f16.f16 "
        "{%0,%1}, {%2,%3,%4,%5}, {%6,%7}, {%0,%1};"
        : "+r"(d[0]), "+r"(d[1])
        : "r"(a[0]), "r"(a[1]), "r"(a[2]), "r"(a[3]), "r"(b[0]), "r"(b[1]));
}
__device__ __forceinline__ void ldsm_x4(uint32_t& r0, uint32_t& r1,
                                        uint32_t& r2, uint32_t& r3,
                                        const void* p) {
    uint32_t addr = (uint32_t)__cvta_generic_to_shared(p);
    asm volatile("ldmatrix.sync.aligned.m8n8.x4.shared.b16 {%0,%1,%2,%3}, [%4];"
                 : "=r"(r0), "=r"(r1), "=r"(r2), "=r"(r3) : "r"(addr));
}
__device__ __forceinline__ void ldsm_x4_t(uint32_t& r0, uint32_t& r1,
                                          uint32_t& r2, uint32_t& r3,
                                          const void* p) {
    uint32_t addr = (uint32_t)__cvta_generic_to_shared(p);
    asm volatile("ldmatrix.sync.aligned.m8n8.x4.trans.shared.b16 {%0,%1,%2,%3}, [%4];"
                 : "=r"(r0), "=r"(r1), "=r"(r2), "=r"(r3) : "r"(addr));
}
__device__ __forceinline__ void cp16(const void* smem, const void* g) {
    uint32_t a = (uint32_t)__cvta_generic_to_shared(smem);
    asm volatile("cp.async.ca.shared.global [%0], [%1], 16;" :: "r"(a), "l"(g));
}
__device__ __forceinline__ void cp4(const void* smem, const void* g) {
    uint32_t a = (uint32_t)__cvta_generic_to_shared(smem);
    asm volatile("cp.async.ca.shared.global [%0], [%1], 4;" :: "r"(a), "l"(g));
}

// ---------------------------------------------------------------------------
// Kernel 1 — HMMA QKV GEMM (unchanged from R13-R15).
// ---------------------------------------------------------------------------
__global__ __launch_bounds__(256)
void qkv_hmma_kernel(const float* __restrict__ x,
                     const float* __restrict__ W_attn,
                     const float* __restrict__ b_attn,
                     char* __restrict__ dbase, int b)
{
    __shared__ __half As[2][128][40];   // [buf][m][k]
    __shared__ __half Ws[2][32][136];   // [buf][k][n] raw, 8-half pad

    const int tid  = threadIdx.x;
    const int warp = tid >> 5, lane = tid & 31;
    const int wm = warp & 3, wn = warp >> 2;
    const int lr = lane >> 2;
    const int lm = lane >> 3, lrr = lane & 7;
    const int rowBase = blockIdx.y * 128;
    const int colBase = blockIdx.x * 128;
    const float* A = x + (size_t)b * SEQ * D_MODEL;

    float acc[2][8][4];
#pragma unroll
    for (int mt = 0; mt < 2; mt++)
#pragma unroll
        for (int nt = 0; nt < 8; nt++)
#pragma unroll
            for (int j = 0; j < 4; j++) acc[mt][nt][j] = 0.f;

    float4 a_pre[4], w_pre[4];

#define QKV_LDG(IT) do {                                                        \
    int k0_ = (IT) * 32;                                                        \
    _Pragma("unroll")                                                           \
    for (int i = 0; i < 4; i++) {                                               \
        int idx = tid + i * 256;                                                \
        int r = idx >> 3, c4 = (idx & 7) << 2;                                  \
        a_pre[i] = *(const float4*)&A[(size_t)(rowBase + r) * D_MODEL + k0_ + c4]; \
    }                                                                           \
    _Pragma("unroll")                                                           \
    for (int i = 0; i < 4; i++) {                                               \
        int idx = tid + i * 256;                                                \
        int kr = idx >> 5, n4 = (idx & 31) << 2;                                \
        w_pre[i] = *(const float4*)&W_attn[(size_t)(k0_ + kr) * 2304 + colBase + n4]; \
    }                                                                           \
} while (0)

#define QKV_STS(BUF) do {                                                       \
    _Pragma("unroll")                                                           \
    for (int i = 0; i < 4; i++) {                                               \
        int idx = tid + i * 256;                                                \
        int r = idx >> 3, c4 = (idx & 7) << 2;                                  \
        *(uint32_t*)&As[BUF][r][c4]     = packh2(a_pre[i].x, a_pre[i].y);       \
        *(uint32_t*)&As[BUF][r][c4 + 2] = packh2(a_pre[i].z, a_pre[i].w);       \
        int kr = idx >> 5, n4 = (idx & 31) << 2;                                \
        *(uint32_t*)&Ws[BUF][kr][n4]     = packh2(w_pre[i].x, w_pre[i].y);      \
        *(uint32_t*)&Ws[BUF][kr][n4 + 2] = packh2(w_pre[i].z, w_pre[i].w);      \
    }                                                                           \
} while (0)

    QKV_LDG(0);
    QKV_STS(0);
    __syncthreads();

    for (int it = 0; it < 24; ++it) {
        const int cur = it & 1;
        const bool more = (it + 1 < 24);
        if (more) QKV_LDG(it + 1);

#pragma unroll
        for (int kc = 0; kc < 32; kc += 16) {
            uint32_t qa[2][4];
#pragma unroll
            for (int mt = 0; mt < 2; mt++) {
                int r = wm * 32 + mt * 16 + lrr + ((lane >> 3) & 1) * 8;
                int c = kc + (lane >> 4) * 8;
                ldsm_x4(qa[mt][0], qa[mt][1], qa[mt][2], qa[mt][3],
                        &As[cur][r][c]);
            }
#pragma unroll
            for (int nbp = 0; nbp < 4; nbp++) {
                int k = kc + (lm & 1) * 8 + lrr;
                int n = wn * 64 + nbp * 16 + (lm >> 1) * 8;
                uint32_t r0, r1, r2, r3;
                ldsm_x4_t(r0, r1, r2, r3, &Ws[cur][k][n]);
                uint32_t wb0[2] = {r0, r1}, wb1[2] = {r2, r3};
                mma16816(acc[0][2 * nbp],     qa[0], wb0);
                mma16816(acc[0][2 * nbp + 1], qa[0], wb1);
                mma16816(acc[1][2 * nbp],     qa[1], wb0);
                mma16816(acc[1][2 * nbp + 1], qa[1], wb1);
            }
        }

        if (more) {
            __syncthreads();
            QKV_STS(1 - cur);
            __syncthreads();
        }
    }
#undef QKV_LDG
#undef QKV_STS

#pragma unroll
    for (int nt = 0; nt < 8; nt++) {
        int gcol = colBase + wn * 64 + nt * 8 + (lane & 3) * 2;
        int which = gcol / 768;
        int cc = gcol - which * 768;
        int h = cc >> 6, d0 = cc & 63;
        float b0 = b_attn[gcol], b1 = b_attn[gcol + 1];
        float sc = (which == 0) ? QSCALE : 1.f;
#pragma unroll
        for (int mt = 0; mt < 2; mt++) {
#pragma unroll
            for (int rh = 0; rh < 2; rh++) {
                int t = rowBase + wm * 32 + mt * 16 + lr + rh * 8;
                float v0 = (acc[mt][nt][rh * 2 + 0] + b0) * sc;
                float v1 = (acc[mt][nt][rh * 2 + 1] + b1) * sc;
                char* pa;
                if (which == 0) {
                    pa = dbase + (size_t)(b * SEQ + t) * 3072 + (size_t)(h * 64 + d0) * 2;
                } else {
                    int c = h * SEQ + t;
                    int p = c / 6, s = c - p * 6;
                    pa = dbase + (size_t)p * 3072 + 1536 + s * 256
                       + (which == 2 ? 128 : 0) + d0 * 2;
                }
                *(uint32_t*)pa = packh2(v0, v1);
            }
        }
    }
}

// ---------------------------------------------------------------------------
// Kernel 2 — tensor-core flash attention: R15 pipeline + S in fp16-accum MMA
// (2x tensor rate for S) + packed-half2 softmax (sub.f16x2 + ex2.f16x2 direct
// into PV A-frags, max via max.f16x2 trees). Masking only on diag/invalid
// tiles, done as bit-inserts of -inf (0xFC00) on the packed regs.
// ---------------------------------------------------------------------------
__global__ __launch_bounds__(128, 4)
void attn_mma_kernel(const int* __restrict__ attn_mask,
                     char* __restrict__ dbase, int b)
{
    const int qt   = (int)gridDim.x - 1 - (int)blockIdx.x;  // heavy first
    const int h    = blockIdx.y;
    const int tid  = threadIdx.x;
    const int warp = tid >> 5, lane = tid & 31;
    const int lr   = lane >> 2;
    const int koff = (lane & 3) * 2;
    const int lm = lane >> 3, lrr = lane & 7;

    __shared__ __half Qs[64][72];
    __shared__ __half Ks[2][64][72];
    __shared__ __half Vs[2][64][72];     // raw [key][dim]
    __shared__ int    msk2[2][64];
    __shared__ int    tflag[64];         // per-key-tile "mask all valid"

    // ---- stage Q tile + precompute mask-tile validity flags ----
#pragma unroll
    for (int i = 0; i < 4; i++) {
        int idx = tid + i * 128;
        int rr = idx >> 3, c8 = (idx & 7) * 8;
        const char* src = dbase + (size_t)(b * SEQ + qt * 64 + rr) * 3072
                        + (size_t)(h * 64 + c8) * 2;
        *(uint4*)&Qs[rr][c8] = *(const uint4*)src;
    }
    if (tid < 64 && tid <= qt) {
        const int4* mrow = (const int4*)(attn_mask + b * SEQ + tid * 64);
        int all = 1;
#pragma unroll
        for (int i = 0; i < 16; i++) {
            int4 v = mrow[i];
            all &= (v.x && v.y && v.z && v.w) ? 1 : 0;
        }
        tflag[tid] = all;
    }
    __syncthreads();

    uint32_t qa[4][4];
    const int qr = warp * 16 + lr;
    {
        int r = warp * 16 + lrr + ((lane >> 3) & 1) * 8;
#pragma unroll
        for (int ks = 0; ks < 4; ks++) {
            int c = ks * 16 + (lane >> 4) * 8;
            ldsm_x4(qa[ks][0], qa[ks][1], qa[ks][2], qa[ks][3], &Qs[r][c]);
        }
    }

    const int q0 = qt * 64 + qr;
    const int q1 = q0 + 8;

    float m0 = -1e30f, m1 = -1e30f;
    float O[8][4];
    float lacc[4] = {0.f, 0.f, 0.f, 0.f};   // l via P@ones MMA
    const uint32_t onesb[2] = {0x3C003C00u, 0x3C003C00u};
#pragma unroll
    for (int nb = 0; nb < 8; nb++)
#pragma unroll
        for (int j = 0; j < 4; j++) O[nb][j] = 0.f;

    // ---- incremental pool addressing (advance 64 keys: p+=10, s+=4 wrap 6) ----
    int pp[4], ss[4];
#pragma unroll
    for (int i = 0; i < 4; i++) {
        int rr = (tid + i * 128) >> 3;
        int c0 = h * SEQ + rr;
        pp[i] = c0 / 6;
        ss[i] = c0 - pp[i] * 6;
    }
    const int* mptr = attn_mask + b * SEQ + tid;   // used by tid<64 only

#define ATT_STAGE(BUF) do {                                                     \
    _Pragma("unroll")                                                           \
    for (int i = 0; i < 4; i++) {                                               \
        int idx = tid + i * 128;                                                \
        int rr = idx >> 3, c8 = (idx & 7) * 8;                                  \
        const char* base = dbase + (size_t)pp[i] * 3072 + 1536 + ss[i] * 256;   \
        cp16(&Ks[BUF][rr][c8], base + c8 * 2);                                  \
        cp16(&Vs[BUF][rr][c8], base + 128 + c8 * 2);                            \
        pp[i] += 10; ss[i] += 4;                                                \
        if (ss[i] >= 6) { ss[i] -= 6; pp[i] += 1; }                             \
    }                                                                           \
    if (tid < 64) cp4(&msk2[BUF][tid], mptr);                                   \
    mptr += 64;                                                                 \
    asm volatile("cp.async.commit_group;");                                     \
} while (0)

    ATT_STAGE(0);

    for (int kt = 0; kt <= qt; kt++) {
        const int cur = kt & 1;
        __syncthreads();                        // buffer 1-cur free to restage
        if (kt < qt) {
            ATT_STAGE(1 - cur);
            asm volatile("cp.async.wait_group 1;");
        } else {
            asm volatile("cp.async.wait_group 0;");
        }
        __syncthreads();

        // ---- S = Q K^T in fp16 accumulate (packed f16x2 output) ----
        uint32_t S2[8][2];
#pragma unroll
        for (int nbp = 0; nbp < 4; nbp++) {
            int n = nbp * 16 + (lm >> 1) * 8 + lrr;
            int k = (lm & 1) * 8;
            uint32_t r0, r1, r2, r3;
            ldsm_x4(r0, r1, r2, r3, &Ks[cur][n][k]);
            uint32_t kb0[2] = {r0, r1}, kb1[2] = {r2, r3};
            mma16816_h_zc(S2[2 * nbp],     qa[0], kb0);
            mma16816_h_zc(S2[2 * nbp + 1], qa[0], kb1);
        }
#pragma unroll
        for (int ks = 1; ks < 4; ks++) {
#pragma unroll
            for (int nbp = 0; nbp < 4; nbp++) {
                int n = nbp * 16 + (lm >> 1) * 8 + lrr;
                int k = ks * 16 + (lm & 1) * 8;
                uint32_t r0, r1, r2, r3;
                ldsm_x4(r0, r1, r2, r3, &Ks[cur][n][k]);
                uint32_t kb0[2] = {r0, r1}, kb1[2] = {r2, r3};
                mma16816_h(S2[2 * nbp],     qa[ks], kb0);
                mma16816_h(S2[2 * nbp + 1], qa[ks], kb1);
            }
        }
        // S2[nb][0] = halves {(qr,cc),(qr,cc+1)}, S2[nb][1] = {(q1,cc),(q1,cc+1)}

        // ---- masking (rare path): insert -inf (0xFC00) into packed halves ----
        const bool diag = (kt == qt);
        const bool allv = (tflag[kt] != 0);
        if (diag || !allv) {
            const int* mk = msk2[cur];
#pragma unroll
            for (int nb = 0; nb < 8; nb++) {
                int cc = nb * 8 + koff;
                int kj = kt * 64 + cc;
                bool ok0 = allv || (mk[cc] != 0);
                bool ok1 = allv || (mk[cc + 1] != 0);
                bool a00 = ok0 && (!diag || kj     <= q0);
                bool a01 = ok1 && (!diag || kj + 1 <= q0);
                bool a10 = ok0 && (!diag || kj     <= q1);
                bool a11 = ok1 && (!diag || kj + 1 <= q1);
                uint32_t r0 = S2[nb][0], r1 = S2[nb][1];
                if (!a00) r0 = (r0 & 0xFFFF0000u) | 0x0000FC00u;
                if (!a01) r0 = (r0 & 0x0000FFFFu) | 0xFC000000u;
                if (!a10) r1 = (r1 & 0xFFFF0000u) | 0x0000FC00u;
                if (!a11) r1 = (r1 & 0x0000FFFFu) | 0xFC000000u;
                S2[nb][0] = r0; S2[nb][1] = r1;
            }
        }

        // ---- online softmax (base-2, scale prefolded), packed half2 ----
        uint32_t mp0 = S2[0][0], mp1 = S2[0][1];
#pragma unroll
        for (int nb = 1; nb < 8; nb++) {
            mp0 = hmax2(mp0, S2[nb][0]);
            mp1 = hmax2(mp1, S2[nb][1]);
        }
        float mx0 = fmaxf(h2f_lo(mp0), h2f_hi(mp0));
        float mx1 = fmaxf(h2f_lo(mp1), h2f_hi(mp1));
        mx0 = fmaxf(mx0, __shfl_xor_sync(0xffffffffu, mx0, 1));
        mx0 = fmaxf(mx0, __shfl_xor_sync(0xffffffffu, mx0, 2));
        mx1 = fmaxf(mx1, __shfl_xor_sync(0xffffffffu, mx1, 1));
        mx1 = fmaxf(mx1, __shfl_xor_sync(0xffffffffu, mx1, 2));
        float m0n = fmaxf(m0, mx0), m1n = fmaxf(m1, mx1);
        const bool nochange =
            __all_sync(0xffffffffu, (m0n == m0) && (m1n == m1));
        float corr0 = ex2(m0 - m0n), corr1 = ex2(m1 - m1n);
        m0 = m0n; m1 = m1n;
        const uint32_t m0h2 = packh2(m0, m0);
        const uint32_t m1h2 = packh2(m1, m1);

        // p = 2^(S-m) directly in f16x2 -> PV A-fragments
        uint32_t pa[4][4];
#pragma unroll
        for (int nb = 0; nb < 8; nb++) {
            int ksv = nb >> 1, hi = (nb & 1) * 2;
            pa[ksv][hi + 0] = hex2h2(hsub2(S2[nb][0], m0h2));
            pa[ksv][hi + 1] = hex2h2(hsub2(S2[nb][1], m1h2));
        }
        if (!nochange) {
#pragma unroll
            for (int nb = 0; nb < 8; nb++) {
                O[nb][0] *= corr0; O[nb][1] *= corr0;
                O[nb][2] *= corr1; O[nb][3] *= corr1;
            }
            lacc[0] *= corr0;
            lacc[2] *= corr1;
        }

        // ---- O += P V ; l += P @ ones ----
#pragma unroll
        for (int ksv = 0; ksv < 4; ksv++) {
            mma16816(lacc, pa[ksv], onesb);
#pragma unroll
            for (int nbp = 0; nbp < 4; nbp++) {
                int key = ksv * 16 + (lm & 1) * 8 + lrr;
                int dim = nbp * 16 + (lm >> 1) * 8;
                uint32_t r0, r1, r2, r3;
                ldsm_x4_t(r0, r1, r2, r3, &Vs[cur][key][dim]);
                uint32_t vb0[2] = {r0, r1}, vb1[2] = {r2, r3};
                mma16816(O[2 * nbp],     pa[ksv], vb0);
                mma16816(O[2 * nbp + 1], pa[ksv], vb1);
            }
        }
    }
#undef ATT_STAGE

    // ---- epilogue (l already fully reduced by the ones-MMA) ----
    float inv0 = 1.f / lacc[0], inv1 = 1.f / lacc[2];

    char* r0p = dbase + (size_t)(b * SEQ + q0) * 3072 + (size_t)(h * 64 + koff) * 2;
    char* r1p = dbase + (size_t)(b * SEQ + q1) * 3072 + (size_t)(h * 64 + koff) * 2;
#pragma unroll
    for (int nb = 0; nb < 8; nb++) {
        *(uint32_t*)(r0p + nb * 16) = packh2(O[nb][0] * inv0, O[nb][1] * inv0);
        *(uint32_t*)(r1p + nb * 16) = packh2(O[nb][2] * inv1, O[nb][3] * inv1);
    }
}

// ---------------------------------------------------------------------------
// Kernel 3 — HMMA proj GEMM (unchanged from R13-R15).
// ---------------------------------------------------------------------------
#define PROJ_SMEM_BYTES (64 * 776 * 2 + 2 * 32 * 136 * 2)

__global__ __launch_bounds__(256)
void proj_hmma_kernel(const char* __restrict__ att_base,
                      const float* __restrict__ W_proj,
                      const float* __restrict__ b_proj,
                      float* __restrict__ out)
{
    extern __shared__ char smem_raw[];
    __half (*ATTs)[776] = (__half(*)[776])smem_raw;
    __half (*Ws)[136]   = (__half(*)[136])(smem_raw + 64 * 776 * 2);

    const int tid  = threadIdx.x;
    const int warp = tid >> 5, lane = tid & 31;
    const int wm = warp & 3, wn = warp >> 2;
    const int lr = lane >> 2;
    const int koff = (lane & 3) * 2;
    const int lm = lane >> 3, lrr = lane & 7;
    const int rowBase = blockIdx.x * 64;

#pragma unroll
    for (int i = 0; i < 24; i++) {
        int idx = tid + i * 256;
        int r = idx / 96, c8 = (idx - r * 96) * 8;
        *(uint4*)&ATTs[r][c8] =
            *(const uint4*)(att_base + (size_t)(rowBase + r) * 3072 + (size_t)c8 * 2);
    }

    float4 w_pre[4];

#define PROJ_LDG(IT, COLB) do {                                                 \
    int k0_ = (IT) * 32;                                                        \
    _Pragma("unroll")                                                           \
    for (int i = 0; i < 4; i++) {                                               \
        int idx = tid + i * 256;                                                \
        int kr = idx >> 5, n4 = (idx & 31) << 2;                                \
        w_pre[i] = *(const float4*)&W_proj[(size_t)(k0_ + kr) * 768 + (COLB) + n4]; \
    }                                                                           \
} while (0)

#define PROJ_STS(BUF) do {                                                      \
    _Pragma("unroll")                                                           \
    for (int i = 0; i < 4; i++) {                                               \
        int idx = tid + i * 256;                                                \
        int kr = idx >> 5, n4 = (idx & 31) << 2;                                \
        *(uint32_t*)&Ws[(BUF) * 32 + kr][n4]     = packh2(w_pre[i].x, w_pre[i].y); \
        *(uint32_t*)&Ws[(BUF) * 32 + kr][n4 + 2] = packh2(w_pre[i].z, w_pre[i].w); \
    }                                                                           \
} while (0)

    for (int chunk = 0; chunk < 6; ++chunk) {
        const int colBase = chunk * 128;
        float acc[8][4];
#pragma unroll
        for (int nt = 0; nt < 8; nt++)
#pragma unroll
            for (int j = 0; j < 4; j++) acc[nt][j] = 0.f;

        __syncthreads();
        PROJ_LDG(0, colBase);
        PROJ_STS(0);
        __syncthreads();

        for (int it = 0; it < 24; ++it) {
            const int cur = it & 1;
            const bool more = (it + 1 < 24);
            if (more) PROJ_LDG(it + 1, colBase);

#pragma unroll
            for (int kc = 0; kc < 32; kc += 16) {
                int ak = it * 32 + kc;
                uint32_t aa[4];
                {
                    int r = wm * 16 + lrr + ((lane >> 3) & 1) * 8;
                    int c = ak + (lane >> 4) * 8;
                    ldsm_x4(aa[0], aa[1], aa[2], aa[3], &ATTs[r][c]);
                }
#pragma unroll
                for (int nbp = 0; nbp < 4; nbp++) {
                    int k = kc + (lm & 1) * 8 + lrr;
                    int n = wn * 64 + nbp * 16 + (lm >> 1) * 8;
                    uint32_t r0, r1, r2, r3;
                    ldsm_x4_t(r0, r1, r2, r3, &Ws[cur * 32 + k][n]);
                    uint32_t wb0[2] = {r0, r1}, wb1[2] = {r2, r3};
                    mma16816(acc[2 * nbp],     aa, wb0);
                    mma16816(acc[2 * nbp + 1], aa, wb1);
                }
            }

            if (more) {
                __syncthreads();
                PROJ_STS(1 - cur);
                __syncthreads();
            }
        }

#pragma unroll
        for (int nt = 0; nt < 8; nt++) {
            int gcol = colBase + wn * 64 + nt * 8 + koff;
            float b0 = b_proj[gcol], b1 = b_proj[gcol + 1];
#pragma unroll
            for (int rh = 0; rh < 2; rh++) {
                int row = rowBase + wm * 16 + lr + rh * 8;
                float2 o;
                o.x = acc[nt][rh * 2 + 0] + b0;
                o.y = acc[nt][rh * 2 + 1] + b1;
                *(float2*)&out[(size_t)row * 768 + gcol] = o;
            }
        }
    }
#undef PROJ_LDG
#undef PROJ_STS
}

// ---------------------------------------------------------------------------
extern "C" void kernel_launch(void* const* d_in, const int* in_sizes, int n_in,
                              void* d_out, int out_size)
{
    const float* x      = (const float*)d_in[0];
    const int*   amask  = (const int*)d_in[1];
    const float* W_attn = (const float*)d_in[2];
    const float* b_attn = (const float*)d_in[3];
    const float* W_proj = (const float*)d_in[4];
    const float* b_proj = (const float*)d_in[5];
    float*       out    = (float*)d_out;
    char*        dbase  = (char*)d_out;

    cudaFuncSetAttribute(proj_hmma_kernel,
                         cudaFuncAttributeMaxDynamicSharedMemorySize,
                         PROJ_SMEM_BYTES);

    for (int b = 0; b < BATCH; b++) {
        qkv_hmma_kernel<<<dim3(2304 / 128, SEQ / 128), 256>>>(x, W_attn, b_attn, dbase, b);
        attn_mma_kernel<<<dim3(SEQ / 64, N_HEADS), 128>>>(amask, dbase, b);
    }
    proj_hmma_kernel<<<M_TOT / 64, 256, PROJ_SMEM_BYTES>>>(dbase, W_proj, b_proj, out);
}